// round 4
// baseline (speedup 1.0000x reference)
#include <cuda_runtime.h>
#include <stdint.h>

#define NROWS 8192
#define DM 14
#define MF 36
#define HH 256
#define FFD 2048
#define EPS 1e-5f
#define TK 512
#define KSTRIDE 514           // padded float2 stride per d2 row
#define TILE_F2 (7 * KSTRIDE) // 3598 float2 per buffer
#define AQ 56                 // queries/rows per CTA (14 warps x 4)

typedef unsigned long long u64;

// persistent scratch (device globals — no allocation allowed)
__device__ __align__(16) float g_h[NROWS * DM];
__device__ __align__(16) float g_q[NROWS * DM];   // pre-scaled by D^-0.5 * log2(e)
__device__ __align__(16) float g_k[NROWS * DM];
__device__ __align__(16) float g_v[NROWS * DM];
__device__ float g_sizef[NROWS];
__device__ float g_qn[NROWS];        // |q_scaled| per row
__device__ float g_kmaxpart[32];     // per-block max |k|^2

// ---------------- f32x2 helpers ----------------
__device__ __forceinline__ u64 f2u(float2 v) { union { float2 f; u64 u; } c; c.f = v; return c.u; }
__device__ __forceinline__ float2 u2f(u64 u) { union { float2 f; u64 u; } c; c.u = u; return c.f; }
__device__ __forceinline__ u64 pack2(float lo, float hi) { float2 v; v.x = lo; v.y = hi; return f2u(v); }
__device__ __forceinline__ u64 fma2(u64 a, u64 b, u64 c) {
    u64 d; asm("fma.rn.f32x2 %0,%1,%2,%3;" : "=l"(d) : "l"(a), "l"(b), "l"(c)); return d;
}
__device__ __forceinline__ u64 mul2(u64 a, u64 b) {
    u64 d; asm("mul.rn.f32x2 %0,%1,%2;" : "=l"(d) : "l"(a), "l"(b)); return d;
}
__device__ __forceinline__ u64 add2(u64 a, u64 b) {
    u64 d; asm("add.rn.f32x2 %0,%1,%2;" : "=l"(d) : "l"(a), "l"(b)); return d;
}
__device__ __forceinline__ float ex2f(float x) {
    float y; asm("ex2.approx.f32 %0,%1;" : "=f"(y) : "f"(x)); return y;
}
__device__ __forceinline__ void cp8(uint32_t dst, const void* src) {
    asm volatile("cp.async.ca.shared.global [%0], [%1], 8;" :: "r"(dst), "l"(src));
}
#define CP_COMMIT() asm volatile("cp.async.commit_group;")
#define CP_WAIT(N)  asm volatile("cp.async.wait_group %0;" :: "n"(N))

// ---------------- warp helpers ----------------
__device__ __forceinline__ float wsum(float v) {
#pragma unroll
    for (int o = 16; o; o >>= 1) v += __shfl_xor_sync(0xffffffffu, v, o);
    return v;
}
__device__ __forceinline__ float wmax(float v) {
#pragma unroll
    for (int o = 16; o; o >>= 1) v = fmaxf(v, __shfl_xor_sync(0xffffffffu, v, o));
    return v;
}

// ---------------- QKV projection ----------------
__global__ void __launch_bounds__(256, 1)
qkv_kernel(const float* __restrict__ x0, int use_x,
           const float* __restrict__ W, const float* __restrict__ b) {
    __shared__ float Ws[42 * 14];
    __shared__ float bs[42];
    __shared__ float hs[64 * 14];
    const float* hin = use_x ? x0 : g_h;
    const int t = threadIdx.x;
    const int rb = blockIdx.x * 64;
    for (int i = t; i < 588; i += 256) Ws[i] = W[i];
    if (t < 42) bs[t] = b[t];
    for (int i = t; i < 64 * 14; i += 256) hs[i] = hin[rb * DM + i];
    __syncthreads();
    const float scale = rsqrtf(14.0f) * 1.44269504f;   // fold log2(e) into q
    for (int idx = t; idx < 64 * 42; idx += 256) {
        int r = idx / 42, c = idx % 42;
        float s = bs[c];
#pragma unroll
        for (int d = 0; d < 14; d++) s = fmaf(hs[r * 14 + d], Ws[c * 14 + d], s);
        int row = rb + r;
        int dd = c % 14;
        if (c < 14)      g_q[row * DM + dd] = s * scale;
        else if (c < 28) g_k[row * DM + dd] = s;
        else             g_v[row * DM + dd] = s;
    }
}

// ---------------- prep: per-row |q|, global max |k|^2 ----------------
__global__ void __launch_bounds__(256, 1)
prep_kernel() {
    __shared__ float sp[8];
    const int t = threadIdx.x, lane = t & 31, warp = t >> 5;
    int r = blockIdx.x * 256 + t;
    float qn = 0.f, kn = 0.f;
#pragma unroll
    for (int d = 0; d < 14; d++) {
        float qf = g_q[r * DM + d]; qn = fmaf(qf, qf, qn);
        float kf = g_k[r * DM + d]; kn = fmaf(kf, kf, kn);
    }
    g_qn[r] = sqrtf(qn);
    kn = wmax(kn);
    if (lane == 0) sp[warp] = kn;
    __syncthreads();
    if (t == 0) {
        float m = sp[0];
#pragma unroll
        for (int w = 1; w < 8; w++) m = fmaxf(m, sp[w]);
        g_kmaxpart[blockIdx.x] = m;
    }
}

// ---------------- attention tile copy (448 threads: 3584 = 448*8) ----------------
__device__ __forceinline__ void tile_cp(uint32_t ksb, uint32_t vsb, int buf, int cb, int t) {
    const float2* gk = ((const float2*)g_k) + cb * 7;
    const float2* gv = ((const float2*)g_v) + cb * 7;
    uint32_t kd = ksb + (uint32_t)buf * TILE_F2 * 8;
    uint32_t vd = vsb + (uint32_t)buf * TILE_F2 * 8;
#pragma unroll
    for (int s = 0; s < 8; s++) {
        int i = t + s * 448;                 // i < 3584
        int kk = i / 7;
        int d2 = i - kk * 7;
        uint32_t off = (uint32_t)(d2 * KSTRIDE + kk) * 8u;
        cp8(kd + off, gk + i);
        cp8(vd + off, gv + i);
    }
}

// ---------------- Flash attention + out-proj + residual + LN1 ----------------
// 147 CTAs x 448 threads (14 warps = RF max); 4 queries/warp; tail clamped.
__global__ void __launch_bounds__(448)
attn_kernel(const float* __restrict__ x0, int use_x,
            const float* __restrict__ Wo, const float* __restrict__ bo,
            const float* __restrict__ lng, const float* __restrict__ lnb) {
    extern __shared__ float sm[];
    float2* Ks2 = (float2*)sm;                 // 2 bufs x 3598 f2
    float2* Vs2 = Ks2 + 2 * TILE_F2;
    float*  as_ = (float*)(Vs2 + 2 * TILE_F2); // 56*16
    float*  wos = as_ + AQ * 16;               // 196
    float*  bos = wos + 196;                   // 14

    const int t = threadIdx.x, lane = t & 31, warp = t >> 5;
    const uint32_t ksb = (uint32_t)__cvta_generic_to_shared(Ks2);
    const uint32_t vsb = (uint32_t)__cvta_generic_to_shared(Vs2);
    const float* hin = use_x ? x0 : g_h;

    if (t < 196) wos[t] = Wo[t];
    if (t < 14)  bos[t] = bo[t];

    float mk2 = 0.f;
#pragma unroll
    for (int i = 0; i < 32; i++) mk2 = fmaxf(mk2, __ldg(g_kmaxpart + i));
    const float maxk = sqrtf(mk2);

    const int qbase = blockIdx.x * AQ;
    const int q0 = warp * 4;

    u64 q[4][7], o[4][7], init2[4];
    float l[4];
#pragma unroll
    for (int qi = 0; qi < 4; qi++) {
        int row = qbase + q0 + qi;
        if (row > NROWS - 1) row = NROWS - 1;
        const float2* qp = ((const float2*)g_q) + row * 7;
#pragma unroll
        for (int d2 = 0; d2 < 7; d2++) {
            q[qi][d2] = f2u(__ldg(qp + d2));
            o[qi][d2] = 0ull;
        }
        init2[qi] = pack2(-__ldg(g_qn + row) * maxk, 0.f);
        l[qi] = 0.f;
    }

    tile_cp(ksb, vsb, 0, 0, t);
    CP_COMMIT();

    for (int tile = 0; tile < 16; tile++) {
        if (tile < 15) {
            tile_cp(ksb, vsb, (tile + 1) & 1, (tile + 1) * TK, t);
            CP_COMMIT();
            CP_WAIT(1);
        } else {
            CP_WAIT(0);
        }
        __syncthreads();

        const float2* Kb = Ks2 + (tile & 1) * TILE_F2;
        const float2* Vb = Vs2 + (tile & 1) * TILE_F2;
#pragma unroll 2
        for (int kk = lane; kk < TK; kk += 32) {
            // QK phase: K d-pairs streamed, 1-2 live at a time
            u64 s2[4];
            {
                u64 kd = f2u(Kb[kk]);
#pragma unroll
                for (int qi = 0; qi < 4; qi++) s2[qi] = fma2(q[qi][0], kd, init2[qi]);
            }
#pragma unroll
            for (int dp = 1; dp < 7; dp++) {
                u64 kd = f2u(Kb[dp * KSTRIDE + kk]);
#pragma unroll
                for (int qi = 0; qi < 4; qi++) s2[qi] = fma2(q[qi][dp], kd, s2[qi]);
            }
            u64 p2[4];
#pragma unroll
            for (int qi = 0; qi < 4; qi++) {
                float2 sf = u2f(s2[qi]);
                float p = ex2f(sf.x + sf.y);
                l[qi] += p;
                p2[qi] = pack2(p, p);
            }
            // AV phase: V d-pairs streamed
#pragma unroll
            for (int dp = 0; dp < 7; dp++) {
                u64 vd = f2u(Vb[dp * KSTRIDE + kk]);
#pragma unroll
                for (int qi = 0; qi < 4; qi++) o[qi][dp] = fma2(p2[qi], vd, o[qi][dp]);
            }
        }
        __syncthreads();
    }

    // cross-lane combine (shared M per query)
#pragma unroll
    for (int qi = 0; qi < 4; qi++) {
        float ll = wsum(l[qi]);
        float av[14];
#pragma unroll
        for (int d2 = 0; d2 < 7; d2++) {
            float2 f = u2f(o[qi][d2]);
            av[2 * d2] = wsum(f.x);
            av[2 * d2 + 1] = wsum(f.y);
        }
        if (lane == 0) {
            float inv = 1.f / ll;
            float* ap = as_ + ((q0 + qi) << 4);
#pragma unroll
            for (int d = 0; d < 14; d++) ap[d] = av[d] * inv;
        }
    }
    __syncthreads();

    // out-projection + residual + LN1
    if (t < AQ) {
        int row = qbase + t;
        if (row < NROWS) {
            float a[14];
#pragma unroll
            for (int d = 0; d < 14; d++) a[d] = as_[(t << 4) + d];
            float pre[14];
            float mu = 0.f;
#pragma unroll
            for (int d2 = 0; d2 < 14; d2++) {
                float ov = bos[d2];
#pragma unroll
                for (int d = 0; d < 14; d++) ov = fmaf(a[d], wos[d2 * 14 + d], ov);
                ov += hin[row * DM + d2];
                pre[d2] = ov;
                mu += ov;
            }
            mu *= (1.f / 14.f);
            float var = 0.f;
#pragma unroll
            for (int d = 0; d < 14; d++) { float z = pre[d] - mu; var = fmaf(z, z, var); }
            var *= (1.f / 14.f);
            float rs = rsqrtf(var + EPS);
#pragma unroll
            for (int d = 0; d < 14; d++)
                g_h[row * DM + d] = (pre[d] - mu) * rs * __ldg(lng + d) + __ldg(lnb + d);
        }
    }
}

// ---------------- Fused FFN (14->2048->14) + residual + LN2 ----------------
// 147 CTAs x 448 threads; warp owns 4 rows, sweeps all 2048 j; dp-major weights
// in smem (contiguous conflict-free LDS.64); tail clamped.
__global__ void __launch_bounds__(448)
ffn_kernel(const float* __restrict__ W1, const float* __restrict__ b1,
           const float* __restrict__ W2, const float* __restrict__ b2,
           const float* __restrict__ lng, const float* __restrict__ lnb) {
    extern __shared__ float sm[];
    float2* W1s = (float2*)sm;          // [dp*2048 + j], 14336 f2
    float2* W2p = W1s + 14336;          // [dp*2048 + j] = (W2[2dp][j], W2[2dp+1][j])

    const int t = threadIdx.x, lane = t & 31, warp = t >> 5;

    {
        const float2* W1g = (const float2*)W1;
        for (int i = t; i < 14336; i += 448) {
            int dp = i >> 11, j = i & 2047;
            W1s[i] = W1g[j * 7 + dp];
            float2 v;
            v.x = __ldg(W2 + (2 * dp) * 2048 + j);
            v.y = __ldg(W2 + (2 * dp + 1) * 2048 + j);
            W2p[i] = v;
        }
    }
    __syncthreads();

    int r0 = blockIdx.x * AQ + warp * 4;
    if (r0 > NROWS - 4) r0 = NROWS - 4;

    u64 hB[4][7];
#pragma unroll
    for (int r = 0; r < 4; r++) {
        const float2* hp = ((const float2*)g_h) + (r0 + r) * 7;
#pragma unroll
        for (int dp = 0; dp < 7; dp++) hB[r][dp] = f2u(__ldg(hp + dp));
    }

    u64 acc[7][4];
#pragma unroll
    for (int dp = 0; dp < 7; dp++)
#pragma unroll
        for (int r = 0; r < 4; r++) acc[dp][r] = 0ull;

    for (int it = 0; it < 64; it++) {
        const int j = it * 32 + lane;
        const float b1j = __ldg(b1 + j);
        u64 s2[4];
        {
            u64 w = f2u(W1s[j]);
#pragma unroll
            for (int r = 0; r < 4; r++) s2[r] = mul2(hB[r][0], w);
        }
#pragma unroll
        for (int dp = 1; dp < 7; dp++) {
            u64 w = f2u(W1s[dp * 2048 + j]);
#pragma unroll
            for (int r = 0; r < 4; r++) s2[r] = fma2(hB[r][dp], w, s2[r]);
        }
        u64 hd[4];
#pragma unroll
        for (int r = 0; r < 4; r++) {
            float2 sf = u2f(s2[r]);
            float hj = fmaxf(sf.x + sf.y + b1j, 0.f);
            hd[r] = pack2(hj, hj);
        }
#pragma unroll
        for (int dp = 0; dp < 7; dp++) {
            u64 w = f2u(W2p[dp * 2048 + j]);
#pragma unroll
            for (int r = 0; r < 4; r++) acc[dp][r] = fma2(hd[r], w, acc[dp][r]);
        }
    }

    // butterfly-reduce 28 u64 accumulators over 32 lanes
#pragma unroll
    for (int off = 16; off; off >>= 1) {
#pragma unroll
        for (int dp = 0; dp < 7; dp++)
#pragma unroll
            for (int r = 0; r < 4; r++) {
                u64 other = __shfl_xor_sync(0xffffffffu, acc[dp][r], off);
                acc[dp][r] = add2(acc[dp][r], other);
            }
    }

    // lanes 0-3 finalize one row each: bias + residual + LN2
#pragma unroll
    for (int r = 0; r < 4; r++) {
        if (lane == r) {
            float pre[14];
            float mu = 0.f;
#pragma unroll
            for (int dp = 0; dp < 7; dp++) {
                float2 a = u2f(acc[dp][r]);
                float2 h2 = u2f(hB[r][dp]);
                float p0 = a.x + __ldg(b2 + 2 * dp) + h2.x;
                float p1 = a.y + __ldg(b2 + 2 * dp + 1) + h2.y;
                pre[2 * dp] = p0; pre[2 * dp + 1] = p1;
                mu += p0 + p1;
            }
            mu *= (1.f / 14.f);
            float var = 0.f;
#pragma unroll
            for (int d = 0; d < 14; d++) { float z = pre[d] - mu; var = fmaf(z, z, var); }
            float rs = rsqrtf(var * (1.f / 14.f) + EPS);
            float* hw = g_h + (r0 + r) * DM;
#pragma unroll
            for (int d = 0; d < 14; d++)
                hw[d] = (pre[d] - mu) * rs * __ldg(lng + d) + __ldg(lnb + d);
        }
    }
}

// ---------------- head 1 ----------------
__global__ void __launch_bounds__(256, 1)
head1_kernel(const float* __restrict__ w1, const float* __restrict__ b1f,
             const float* __restrict__ w2, const float* __restrict__ b2f,
             float* __restrict__ out) {
    int n = blockIdx.x * 256 + threadIdx.x;
    float h[14];
#pragma unroll
    for (int d = 0; d < 14; d++) h[d] = g_h[n * DM + d];
    float size = __ldg(b2f);
#pragma unroll
    for (int d2 = 0; d2 < 14; d2++) {
        float s = __ldg(b1f + d2);
#pragma unroll
        for (int d = 0; d < 14; d++) s = fmaf(h[d], __ldg(w1 + d2 * 14 + d), s);
        size = fmaf(s, __ldg(w2 + d2), size);
    }
    out[n] = size;
    g_sizef[n] = (float)(int)size;
}

// ---------------- head 2: 51->256->256->1 ----------------
__global__ void __launch_bounds__(256, 1)
head2_kernel(const float* __restrict__ x, const float* __restrict__ y,
             const float* __restrict__ w3, const float* __restrict__ b3,
             const float* __restrict__ w4, const float* __restrict__ b4,
             const float* __restrict__ w5, const float* __restrict__ b5,
             float* __restrict__ out) {
    extern __shared__ float sm[];
    float* w3s   = sm;             // 13056 [t*51+i]
    float* ins   = w3s + 13056;    // 816
    float* red   = ins + 816;      // 128
    float* r1f   = red + 128;      // 256 x 9 f2 = 4608 floats
    float* w4s   = r1f + 4608;     // 256 x 65 = 16640

    const int t = threadIdx.x, lane = t & 31, warp = t >> 5;
    const int rbase = blockIdx.x * 16;
    for (int i = t; i < 13056; i += 256) w3s[i] = w3[i];
    for (int i = t; i < 16 * 51; i += 256) {
        int r = i / 51, c = i % 51, row = rbase + r;
        float v;
        if (c == 0)      v = g_sizef[row];
        else if (c < 15) v = x[row * DM + c - 1];
        else             v = y[row * MF + c - 15];
        ins[i] = v;
    }
    __syncthreads();

    float r1a[16];
    float b3t = __ldg(b3 + t);
#pragma unroll
    for (int r = 0; r < 16; r++) r1a[r] = b3t;
    for (int i = 0; i < 51; i++) {
        float w = w3s[t * 51 + i];
#pragma unroll
        for (int r = 0; r < 16; r++) r1a[r] = fmaf(ins[r * 51 + i], w, r1a[r]);
    }
#pragma unroll
    for (int rp = 0; rp < 8; rp++) {
        float2 v;
        v.x = fmaxf(r1a[2 * rp], 0.f);
        v.y = fmaxf(r1a[2 * rp + 1], 0.f);
        ((float2*)r1f)[t * 9 + rp] = v;
    }
    __syncthreads();

    u64 r2a2[8];
    float b4t = __ldg(b4 + t);
#pragma unroll
    for (int rp = 0; rp < 8; rp++) r2a2[rp] = pack2(b4t, b4t);
    for (int c = 0; c < 4; c++) {
        for (int i = t; i < 256 * 64; i += 256) {
            int o = i >> 6, jj = i & 63;
            w4s[o * 65 + jj] = __ldg(w4 + o * 256 + c * 64 + jj);
        }
        __syncthreads();
#pragma unroll 4
        for (int jj = 0; jj < 64; jj++) {
            float w = w4s[t * 65 + jj];
            u64 w2p = pack2(w, w);
            const float2* rp1 = ((const float2*)r1f) + (c * 64 + jj) * 9;
#pragma unroll
            for (int rp = 0; rp < 8; rp++)
                r2a2[rp] = fma2(f2u(rp1[rp]), w2p, r2a2[rp]);
        }
        __syncthreads();
    }

    float w5t = __ldg(w5 + t);
#pragma unroll
    for (int rp = 0; rp < 8; rp++) {
        float2 f = u2f(r2a2[rp]);
        float v0 = wsum(fmaxf(f.x, 0.f) * w5t);
        float v1 = wsum(fmaxf(f.y, 0.f) * w5t);
        if (lane == 0) {
            red[warp * 16 + 2 * rp] = v0;
            red[warp * 16 + 2 * rp + 1] = v1;
        }
    }
    __syncthreads();
    if (t < 16) {
        float s = __ldg(b5);
        for (int w = 0; w < 8; w++) s += red[w * 16 + t];
        int row = rbase + t;
        out[NROWS + row] = (g_sizef[row] != 0.f) ? s : 0.f;
    }
}

// ---------------- launcher ----------------
extern "C" void kernel_launch(void* const* d_in, const int* in_sizes, int n_in,
                              void* d_out, int out_size) {
    const float* x    = (const float*)d_in[0];
    const float* y    = (const float*)d_in[1];
    const float* wqkv = (const float*)d_in[2];
    const float* bqkv = (const float*)d_in[3];
    const float* wo   = (const float*)d_in[4];
    const float* bo   = (const float*)d_in[5];
    const float* ln1g = (const float*)d_in[6];
    const float* ln1b = (const float*)d_in[7];
    const float* ffw1 = (const float*)d_in[8];
    const float* ffb1 = (const float*)d_in[9];
    const float* ffw2 = (const float*)d_in[10];
    const float* ffb2 = (const float*)d_in[11];
    const float* ln2g = (const float*)d_in[12];
    const float* ln2b = (const float*)d_in[13];
    const float* fc1w = (const float*)d_in[14];
    const float* fc1b = (const float*)d_in[15];
    const float* fc2w = (const float*)d_in[16];
    const float* fc2b = (const float*)d_in[17];
    const float* fc3w = (const float*)d_in[18];
    const float* fc3b = (const float*)d_in[19];
    const float* fc4w = (const float*)d_in[20];
    const float* fc4b = (const float*)d_in[21];
    const float* fc5w = (const float*)d_in[22];
    const float* fc5b = (const float*)d_in[23];
    float* out = (float*)d_out;

    const int attn_smem = 4 * TILE_F2 * 8 + (AQ * 16 + 196 + 16) * (int)sizeof(float);
    const int ffn_smem  = 14336 * 2 * 8;   // 229376 B
    const int h2_smem   = (13056 + 816 + 128 + 4608 + 16640) * (int)sizeof(float);
    cudaFuncSetAttribute(attn_kernel,  cudaFuncAttributeMaxDynamicSharedMemorySize, attn_smem);
    cudaFuncSetAttribute(ffn_kernel,   cudaFuncAttributeMaxDynamicSharedMemorySize, ffn_smem);
    cudaFuncSetAttribute(head2_kernel, cudaFuncAttributeMaxDynamicSharedMemorySize, h2_smem);

    const int grid = (NROWS + AQ - 1) / AQ;   // 147
    for (int l = 0; l < 2; l++) {
        qkv_kernel<<<128, 256>>>(x, (l == 0) ? 1 : 0, wqkv + l * 588, bqkv + l * 42);
        prep_kernel<<<32, 256>>>();
        attn_kernel<<<grid, 448, attn_smem>>>(x, (l == 0) ? 1 : 0,
                                              wo + l * 196, bo + l * 14,
                                              ln1g + l * 14, ln1b + l * 14);
        ffn_kernel<<<grid, 448, ffn_smem>>>(ffw1 + l * 28672, ffb1 + l * 2048,
                                            ffw2 + l * 28672, ffb2 + l * 14,
                                            ln2g + l * 14, ln2b + l * 14);
    }
    head1_kernel<<<32, 256>>>(fc1w, fc1b, fc2w, fc2b, out);
    head2_kernel<<<512, 256, h2_smem>>>(x, y, fc3w, fc3b, fc4w, fc4b, fc5w, fc5b, out);
}

// round 5
// speedup vs baseline: 1.0032x; 1.0032x over previous
#include <cuda_runtime.h>
#include <stdint.h>

#define NROWS 8192
#define DM 14
#define MF 36
#define HH 256
#define FFD 2048
#define EPS 1e-5f
#define TK 512
#define KSTRIDE 514           // padded float2 stride per d2 row
#define TILE_F2 (7 * KSTRIDE) // 3598 float2 per buffer
#define AQ 56                 // queries/rows per CTA (14 warps x 4)

typedef unsigned long long u64;

// persistent scratch (device globals — no allocation allowed)
__device__ __align__(16) float g_h[NROWS * DM];
__device__ __align__(16) float g_q[NROWS * DM];   // pre-scaled by D^-0.5 * log2(e)
__device__ __align__(16) float g_k[NROWS * DM];
__device__ __align__(16) float g_v[NROWS * DM];
__device__ float g_sizef[NROWS];
__device__ float g_qn[NROWS];        // |q_scaled| per row
__device__ float g_kmaxpart[32];     // per-block max |k|^2

// ---------------- f32x2 helpers ----------------
__device__ __forceinline__ u64 f2u(float2 v) { union { float2 f; u64 u; } c; c.f = v; return c.u; }
__device__ __forceinline__ float2 u2f(u64 u) { union { float2 f; u64 u; } c; c.u = u; return c.f; }
__device__ __forceinline__ u64 pack2(float lo, float hi) { float2 v; v.x = lo; v.y = hi; return f2u(v); }
__device__ __forceinline__ u64 fma2(u64 a, u64 b, u64 c) {
    u64 d; asm("fma.rn.f32x2 %0,%1,%2,%3;" : "=l"(d) : "l"(a), "l"(b), "l"(c)); return d;
}
__device__ __forceinline__ u64 mul2(u64 a, u64 b) {
    u64 d; asm("mul.rn.f32x2 %0,%1,%2;" : "=l"(d) : "l"(a), "l"(b)); return d;
}
__device__ __forceinline__ u64 add2(u64 a, u64 b) {
    u64 d; asm("add.rn.f32x2 %0,%1,%2;" : "=l"(d) : "l"(a), "l"(b)); return d;
}
__device__ __forceinline__ float ex2f(float x) {
    float y; asm("ex2.approx.f32 %0,%1;" : "=f"(y) : "f"(x)); return y;
}
__device__ __forceinline__ void cp8(uint32_t dst, const void* src) {
    asm volatile("cp.async.ca.shared.global [%0], [%1], 8;" :: "r"(dst), "l"(src));
}
#define CP_COMMIT() asm volatile("cp.async.commit_group;")
#define CP_WAIT(N)  asm volatile("cp.async.wait_group %0;" :: "n"(N))

// ---------------- warp helpers ----------------
__device__ __forceinline__ float wsum(float v) {
#pragma unroll
    for (int o = 16; o; o >>= 1) v += __shfl_xor_sync(0xffffffffu, v, o);
    return v;
}
__device__ __forceinline__ float wmax(float v) {
#pragma unroll
    for (int o = 16; o; o >>= 1) v = fmaxf(v, __shfl_xor_sync(0xffffffffu, v, o));
    return v;
}

// ---------------- QKV projection ----------------
__global__ void __launch_bounds__(256, 1)
qkv_kernel(const float* __restrict__ x0, int use_x,
           const float* __restrict__ W, const float* __restrict__ b) {
    __shared__ float Ws[42 * 14];
    __shared__ float bs[42];
    __shared__ float hs[64 * 14];
    const float* hin = use_x ? x0 : g_h;
    const int t = threadIdx.x;
    const int rb = blockIdx.x * 64;
    for (int i = t; i < 588; i += 256) Ws[i] = W[i];
    if (t < 42) bs[t] = b[t];
    for (int i = t; i < 64 * 14; i += 256) hs[i] = hin[rb * DM + i];
    __syncthreads();
    const float scale = rsqrtf(14.0f) * 1.44269504f;   // fold log2(e) into q
    for (int idx = t; idx < 64 * 42; idx += 256) {
        int r = idx / 42, c = idx % 42;
        float s = bs[c];
#pragma unroll
        for (int d = 0; d < 14; d++) s = fmaf(hs[r * 14 + d], Ws[c * 14 + d], s);
        int row = rb + r;
        int dd = c % 14;
        if (c < 14)      g_q[row * DM + dd] = s * scale;
        else if (c < 28) g_k[row * DM + dd] = s;
        else             g_v[row * DM + dd] = s;
    }
}

// ---------------- prep: per-row |q|, global max |k|^2 ----------------
__global__ void __launch_bounds__(256, 1)
prep_kernel() {
    __shared__ float sp[8];
    const int t = threadIdx.x, lane = t & 31, warp = t >> 5;
    int r = blockIdx.x * 256 + t;
    float qn = 0.f, kn = 0.f;
#pragma unroll
    for (int d = 0; d < 14; d++) {
        float qf = g_q[r * DM + d]; qn = fmaf(qf, qf, qn);
        float kf = g_k[r * DM + d]; kn = fmaf(kf, kf, kn);
    }
    g_qn[r] = sqrtf(qn);
    kn = wmax(kn);
    if (lane == 0) sp[warp] = kn;
    __syncthreads();
    if (t == 0) {
        float m = sp[0];
#pragma unroll
        for (int w = 1; w < 8; w++) m = fmaxf(m, sp[w]);
        g_kmaxpart[blockIdx.x] = m;
    }
}

// ---------------- attention tile copy (448 threads: 3584 = 448*8) ----------------
__device__ __forceinline__ void tile_cp(uint32_t ksb, uint32_t vsb, int buf, int cb, int t) {
    const float2* gk = ((const float2*)g_k) + cb * 7;
    const float2* gv = ((const float2*)g_v) + cb * 7;
    uint32_t kd = ksb + (uint32_t)buf * TILE_F2 * 8;
    uint32_t vd = vsb + (uint32_t)buf * TILE_F2 * 8;
#pragma unroll
    for (int s = 0; s < 8; s++) {
        int i = t + s * 448;                 // i < 3584
        int kk = i / 7;
        int d2 = i - kk * 7;
        uint32_t off = (uint32_t)(d2 * KSTRIDE + kk) * 8u;
        cp8(kd + off, gk + i);
        cp8(vd + off, gv + i);
    }
}

// ---------------- Flash attention + out-proj + residual + LN1 ----------------
// 147 CTAs x 448 threads (14 warps = RF max); 4 queries/warp; tail clamped.
__global__ void __launch_bounds__(448)
attn_kernel(const float* __restrict__ x0, int use_x,
            const float* __restrict__ Wo, const float* __restrict__ bo,
            const float* __restrict__ lng, const float* __restrict__ lnb) {
    extern __shared__ float sm[];
    float2* Ks2 = (float2*)sm;                 // 2 bufs x 3598 f2
    float2* Vs2 = Ks2 + 2 * TILE_F2;
    float*  as_ = (float*)(Vs2 + 2 * TILE_F2); // 56*16
    float*  wos = as_ + AQ * 16;               // 196
    float*  bos = wos + 196;                   // 14

    const int t = threadIdx.x, lane = t & 31, warp = t >> 5;
    const uint32_t ksb = (uint32_t)__cvta_generic_to_shared(Ks2);
    const uint32_t vsb = (uint32_t)__cvta_generic_to_shared(Vs2);
    const float* hin = use_x ? x0 : g_h;

    if (t < 196) wos[t] = Wo[t];
    if (t < 14)  bos[t] = bo[t];

    float mk2 = 0.f;
#pragma unroll
    for (int i = 0; i < 32; i++) mk2 = fmaxf(mk2, __ldg(g_kmaxpart + i));
    const float maxk = sqrtf(mk2);

    const int qbase = blockIdx.x * AQ;
    const int q0 = warp * 4;

    u64 q[4][7], o[4][7], init2[4];
    float l[4];
#pragma unroll
    for (int qi = 0; qi < 4; qi++) {
        int row = qbase + q0 + qi;
        if (row > NROWS - 1) row = NROWS - 1;
        const float2* qp = ((const float2*)g_q) + row * 7;
#pragma unroll
        for (int d2 = 0; d2 < 7; d2++) {
            q[qi][d2] = f2u(__ldg(qp + d2));
            o[qi][d2] = 0ull;
        }
        init2[qi] = pack2(-__ldg(g_qn + row) * maxk, 0.f);
        l[qi] = 0.f;
    }

    tile_cp(ksb, vsb, 0, 0, t);
    CP_COMMIT();

    for (int tile = 0; tile < 16; tile++) {
        if (tile < 15) {
            tile_cp(ksb, vsb, (tile + 1) & 1, (tile + 1) * TK, t);
            CP_COMMIT();
            CP_WAIT(1);
        } else {
            CP_WAIT(0);
        }
        __syncthreads();

        const float2* Kb = Ks2 + (tile & 1) * TILE_F2;
        const float2* Vb = Vs2 + (tile & 1) * TILE_F2;
#pragma unroll 2
        for (int kk = lane; kk < TK; kk += 32) {
            // QK phase: K d-pairs streamed, 1-2 live at a time
            u64 s2[4];
            {
                u64 kd = f2u(Kb[kk]);
#pragma unroll
                for (int qi = 0; qi < 4; qi++) s2[qi] = fma2(q[qi][0], kd, init2[qi]);
            }
#pragma unroll
            for (int dp = 1; dp < 7; dp++) {
                u64 kd = f2u(Kb[dp * KSTRIDE + kk]);
#pragma unroll
                for (int qi = 0; qi < 4; qi++) s2[qi] = fma2(q[qi][dp], kd, s2[qi]);
            }
            u64 p2[4];
#pragma unroll
            for (int qi = 0; qi < 4; qi++) {
                float2 sf = u2f(s2[qi]);
                float p = ex2f(sf.x + sf.y);
                l[qi] += p;
                p2[qi] = pack2(p, p);
            }
            // AV phase: V d-pairs streamed
#pragma unroll
            for (int dp = 0; dp < 7; dp++) {
                u64 vd = f2u(Vb[dp * KSTRIDE + kk]);
#pragma unroll
                for (int qi = 0; qi < 4; qi++) o[qi][dp] = fma2(p2[qi], vd, o[qi][dp]);
            }
        }
        __syncthreads();
    }

    // cross-lane combine (shared M per query)
#pragma unroll
    for (int qi = 0; qi < 4; qi++) {
        float ll = wsum(l[qi]);
        float av[14];
#pragma unroll
        for (int d2 = 0; d2 < 7; d2++) {
            float2 f = u2f(o[qi][d2]);
            av[2 * d2] = wsum(f.x);
            av[2 * d2 + 1] = wsum(f.y);
        }
        if (lane == 0) {
            float inv = 1.f / ll;
            float* ap = as_ + ((q0 + qi) << 4);
#pragma unroll
            for (int d = 0; d < 14; d++) ap[d] = av[d] * inv;
        }
    }
    __syncthreads();

    // out-projection + residual + LN1
    if (t < AQ) {
        int row = qbase + t;
        if (row < NROWS) {
            float a[14];
#pragma unroll
            for (int d = 0; d < 14; d++) a[d] = as_[(t << 4) + d];
            float pre[14];
            float mu = 0.f;
#pragma unroll
            for (int d2 = 0; d2 < 14; d2++) {
                float ov = bos[d2];
#pragma unroll
                for (int d = 0; d < 14; d++) ov = fmaf(a[d], wos[d2 * 14 + d], ov);
                ov += hin[row * DM + d2];
                pre[d2] = ov;
                mu += ov;
            }
            mu *= (1.f / 14.f);
            float var = 0.f;
#pragma unroll
            for (int d = 0; d < 14; d++) { float z = pre[d] - mu; var = fmaf(z, z, var); }
            var *= (1.f / 14.f);
            float rs = rsqrtf(var + EPS);
#pragma unroll
            for (int d = 0; d < 14; d++)
                g_h[row * DM + d] = (pre[d] - mu) * rs * __ldg(lng + d) + __ldg(lnb + d);
        }
    }
}

// ---------------- Fused FFN (14->2048->14) + residual + LN2 ----------------
// 147 CTAs x 448 threads; warp owns 4 rows, sweeps all 2048 j; dp-major weights
// in smem (contiguous conflict-free LDS.64); tail clamped.
__global__ void __launch_bounds__(448)
ffn_kernel(const float* __restrict__ W1, const float* __restrict__ b1,
           const float* __restrict__ W2, const float* __restrict__ b2,
           const float* __restrict__ lng, const float* __restrict__ lnb) {
    extern __shared__ float sm[];
    float2* W1s = (float2*)sm;          // [dp*2048 + j], 14336 f2
    float2* W2p = W1s + 14336;          // [dp*2048 + j] = (W2[2dp][j], W2[2dp+1][j])

    const int t = threadIdx.x, lane = t & 31, warp = t >> 5;

    {
        const float2* W1g = (const float2*)W1;
        for (int i = t; i < 14336; i += 448) {
            int dp = i >> 11, j = i & 2047;
            W1s[i] = W1g[j * 7 + dp];
            float2 v;
            v.x = __ldg(W2 + (2 * dp) * 2048 + j);
            v.y = __ldg(W2 + (2 * dp + 1) * 2048 + j);
            W2p[i] = v;
        }
    }
    __syncthreads();

    int r0 = blockIdx.x * AQ + warp * 4;
    if (r0 > NROWS - 4) r0 = NROWS - 4;

    u64 hB[4][7];
#pragma unroll
    for (int r = 0; r < 4; r++) {
        const float2* hp = ((const float2*)g_h) + (r0 + r) * 7;
#pragma unroll
        for (int dp = 0; dp < 7; dp++) hB[r][dp] = f2u(__ldg(hp + dp));
    }

    u64 acc[7][4];
#pragma unroll
    for (int dp = 0; dp < 7; dp++)
#pragma unroll
        for (int r = 0; r < 4; r++) acc[dp][r] = 0ull;

    for (int it = 0; it < 64; it++) {
        const int j = it * 32 + lane;
        const float b1j = __ldg(b1 + j);
        u64 s2[4];
        {
            u64 w = f2u(W1s[j]);
#pragma unroll
            for (int r = 0; r < 4; r++) s2[r] = mul2(hB[r][0], w);
        }
#pragma unroll
        for (int dp = 1; dp < 7; dp++) {
            u64 w = f2u(W1s[dp * 2048 + j]);
#pragma unroll
            for (int r = 0; r < 4; r++) s2[r] = fma2(hB[r][dp], w, s2[r]);
        }
        u64 hd[4];
#pragma unroll
        for (int r = 0; r < 4; r++) {
            float2 sf = u2f(s2[r]);
            float hj = fmaxf(sf.x + sf.y + b1j, 0.f);
            hd[r] = pack2(hj, hj);
        }
#pragma unroll
        for (int dp = 0; dp < 7; dp++) {
            u64 w = f2u(W2p[dp * 2048 + j]);
#pragma unroll
            for (int r = 0; r < 4; r++) acc[dp][r] = fma2(hd[r], w, acc[dp][r]);
        }
    }

    // butterfly-reduce 28 u64 accumulators over 32 lanes
#pragma unroll
    for (int off = 16; off; off >>= 1) {
#pragma unroll
        for (int dp = 0; dp < 7; dp++)
#pragma unroll
            for (int r = 0; r < 4; r++) {
                u64 other = __shfl_xor_sync(0xffffffffu, acc[dp][r], off);
                acc[dp][r] = add2(acc[dp][r], other);
            }
    }

    // lanes 0-3 finalize one row each: bias + residual + LN2
#pragma unroll
    for (int r = 0; r < 4; r++) {
        if (lane == r) {
            float pre[14];
            float mu = 0.f;
#pragma unroll
            for (int dp = 0; dp < 7; dp++) {
                float2 a = u2f(acc[dp][r]);
                float2 h2 = u2f(hB[r][dp]);
                float p0 = a.x + __ldg(b2 + 2 * dp) + h2.x;
                float p1 = a.y + __ldg(b2 + 2 * dp + 1) + h2.y;
                pre[2 * dp] = p0; pre[2 * dp + 1] = p1;
                mu += p0 + p1;
            }
            mu *= (1.f / 14.f);
            float var = 0.f;
#pragma unroll
            for (int d = 0; d < 14; d++) { float z = pre[d] - mu; var = fmaf(z, z, var); }
            float rs = rsqrtf(var * (1.f / 14.f) + EPS);
            float* hw = g_h + (r0 + r) * DM;
#pragma unroll
            for (int d = 0; d < 14; d++)
                hw[d] = (pre[d] - mu) * rs * __ldg(lng + d) + __ldg(lnb + d);
        }
    }
}

// ---------------- head 1 ----------------
__global__ void __launch_bounds__(256, 1)
head1_kernel(const float* __restrict__ w1, const float* __restrict__ b1f,
             const float* __restrict__ w2, const float* __restrict__ b2f,
             float* __restrict__ out) {
    int n = blockIdx.x * 256 + threadIdx.x;
    float h[14];
#pragma unroll
    for (int d = 0; d < 14; d++) h[d] = g_h[n * DM + d];
    float size = __ldg(b2f);
#pragma unroll
    for (int d2 = 0; d2 < 14; d2++) {
        float s = __ldg(b1f + d2);
#pragma unroll
        for (int d = 0; d < 14; d++) s = fmaf(h[d], __ldg(w1 + d2 * 14 + d), s);
        size = fmaf(s, __ldg(w2 + d2), size);
    }
    out[n] = size;
    g_sizef[n] = (float)(int)size;
}

// ---------------- head 2: 51->256->256->1 ----------------
__global__ void __launch_bounds__(256, 1)
head2_kernel(const float* __restrict__ x, const float* __restrict__ y,
             const float* __restrict__ w3, const float* __restrict__ b3,
             const float* __restrict__ w4, const float* __restrict__ b4,
             const float* __restrict__ w5, const float* __restrict__ b5,
             float* __restrict__ out) {
    extern __shared__ float sm[];
    float* w3s   = sm;             // 13056 [t*51+i]
    float* ins   = w3s + 13056;    // 816
    float* red   = ins + 816;      // 128
    float* r1f   = red + 128;      // 256 x 9 f2 = 4608 floats
    float* w4s   = r1f + 4608;     // 256 x 65 = 16640

    const int t = threadIdx.x, lane = t & 31, warp = t >> 5;
    const int rbase = blockIdx.x * 16;
    for (int i = t; i < 13056; i += 256) w3s[i] = w3[i];
    for (int i = t; i < 16 * 51; i += 256) {
        int r = i / 51, c = i % 51, row = rbase + r;
        float v;
        if (c == 0)      v = g_sizef[row];
        else if (c < 15) v = x[row * DM + c - 1];
        else             v = y[row * MF + c - 15];
        ins[i] = v;
    }
    __syncthreads();

    float r1a[16];
    float b3t = __ldg(b3 + t);
#pragma unroll
    for (int r = 0; r < 16; r++) r1a[r] = b3t;
    for (int i = 0; i < 51; i++) {
        float w = w3s[t * 51 + i];
#pragma unroll
        for (int r = 0; r < 16; r++) r1a[r] = fmaf(ins[r * 51 + i], w, r1a[r]);
    }
#pragma unroll
    for (int rp = 0; rp < 8; rp++) {
        float2 v;
        v.x = fmaxf(r1a[2 * rp], 0.f);
        v.y = fmaxf(r1a[2 * rp + 1], 0.f);
        ((float2*)r1f)[t * 9 + rp] = v;
    }
    __syncthreads();

    u64 r2a2[8];
    float b4t = __ldg(b4 + t);
#pragma unroll
    for (int rp = 0; rp < 8; rp++) r2a2[rp] = pack2(b4t, b4t);
    for (int c = 0; c < 4; c++) {
        for (int i = t; i < 256 * 64; i += 256) {
            int o = i >> 6, jj = i & 63;
            w4s[o * 65 + jj] = __ldg(w4 + o * 256 + c * 64 + jj);
        }
        __syncthreads();
#pragma unroll 4
        for (int jj = 0; jj < 64; jj++) {
            float w = w4s[t * 65 + jj];
            u64 w2p = pack2(w, w);
            const float2* rp1 = ((const float2*)r1f) + (c * 64 + jj) * 9;
#pragma unroll
            for (int rp = 0; rp < 8; rp++)
                r2a2[rp] = fma2(f2u(rp1[rp]), w2p, r2a2[rp]);
        }
        __syncthreads();
    }

    float w5t = __ldg(w5 + t);
#pragma unroll
    for (int rp = 0; rp < 8; rp++) {
        float2 f = u2f(r2a2[rp]);
        float v0 = wsum(fmaxf(f.x, 0.f) * w5t);
        float v1 = wsum(fmaxf(f.y, 0.f) * w5t);
        if (lane == 0) {
            red[warp * 16 + 2 * rp] = v0;
            red[warp * 16 + 2 * rp + 1] = v1;
        }
    }
    __syncthreads();
    if (t < 16) {
        float s = __ldg(b5);
        for (int w = 0; w < 8; w++) s += red[w * 16 + t];
        int row = rbase + t;
        out[NROWS + row] = (g_sizef[row] != 0.f) ? s : 0.f;
    }
}

// ---------------- launcher ----------------
extern "C" void kernel_launch(void* const* d_in, const int* in_sizes, int n_in,
                              void* d_out, int out_size) {
    const float* x    = (const float*)d_in[0];
    const float* y    = (const float*)d_in[1];
    const float* wqkv = (const float*)d_in[2];
    const float* bqkv = (const float*)d_in[3];
    const float* wo   = (const float*)d_in[4];
    const float* bo   = (const float*)d_in[5];
    const float* ln1g = (const float*)d_in[6];
    const float* ln1b = (const float*)d_in[7];
    const float* ffw1 = (const float*)d_in[8];
    const float* ffb1 = (const float*)d_in[9];
    const float* ffw2 = (const float*)d_in[10];
    const float* ffb2 = (const float*)d_in[11];
    const float* ln2g = (const float*)d_in[12];
    const float* ln2b = (const float*)d_in[13];
    const float* fc1w = (const float*)d_in[14];
    const float* fc1b = (const float*)d_in[15];
    const float* fc2w = (const float*)d_in[16];
    const float* fc2b = (const float*)d_in[17];
    const float* fc3w = (const float*)d_in[18];
    const float* fc3b = (const float*)d_in[19];
    const float* fc4w = (const float*)d_in[20];
    const float* fc4b = (const float*)d_in[21];
    const float* fc5w = (const float*)d_in[22];
    const float* fc5b = (const float*)d_in[23];
    float* out = (float*)d_out;

    const int attn_smem = 4 * TILE_F2 * 8 + (AQ * 16 + 196 + 16) * (int)sizeof(float);
    const int ffn_smem  = 14336 * 2 * 8;   // 229376 B
    const int h2_smem   = (13056 + 816 + 128 + 4608 + 16640) * (int)sizeof(float);
    cudaFuncSetAttribute(attn_kernel,  cudaFuncAttributeMaxDynamicSharedMemorySize, attn_smem);
    cudaFuncSetAttribute(ffn_kernel,   cudaFuncAttributeMaxDynamicSharedMemorySize, ffn_smem);
    cudaFuncSetAttribute(head2_kernel, cudaFuncAttributeMaxDynamicSharedMemorySize, h2_smem);

    const int grid = (NROWS + AQ - 1) / AQ;   // 147
    for (int l = 0; l < 2; l++) {
        qkv_kernel<<<128, 256>>>(x, (l == 0) ? 1 : 0, wqkv + l * 588, bqkv + l * 42);
        prep_kernel<<<32, 256>>>();
        attn_kernel<<<grid, 448, attn_smem>>>(x, (l == 0) ? 1 : 0,
                                              wo + l * 196, bo + l * 14,
                                              ln1g + l * 14, ln1b + l * 14);
        ffn_kernel<<<grid, 448, ffn_smem>>>(ffw1 + l * 28672, ffb1 + l * 2048,
                                            ffw2 + l * 28672, ffb2 + l * 14,
                                            ln2g + l * 14, ln2b + l * 14);
    }
    head1_kernel<<<32, 256>>>(fc1w, fc1b, fc2w, fc2b, out);
    head2_kernel<<<512, 256, h2_smem>>>(x, y, fc3w, fc3b, fc4w, fc4b, fc5w, fc5b, out);
}

// round 7
// speedup vs baseline: 1.6121x; 1.6070x over previous
#include <cuda_runtime.h>
#include <cuda_fp16.h>
#include <stdint.h>

#define NROWS 8192
#define DM 14
#define MF 36
#define EPS 1e-5f
typedef unsigned long long u64;

__device__ __align__(16) float g_h[NROWS * DM];
__device__ __align__(16) float g_q[NROWS * DM];   // pre-scaled by D^-0.5*log2(e)
__device__ __align__(16) float g_k[NROWS * DM];
__device__ __align__(16) float g_v[NROWS * DM];
__device__ __align__(16) float g_part[2 * NROWS * 16];
__device__ __align__(16) __half g_kp[4 * NROWS * 8];  // [arr][key][8] f16
__device__ __align__(16) __half g_vt[32][NROWS];      // [dim-ish][key] f16
__device__ float g_sizef[NROWS];
__device__ float g_qn[NROWS];
__device__ float g_kmaxpart[32];

// ---- f32x2 helpers ----
__device__ __forceinline__ u64 f2u(float2 v) { union { float2 f; u64 u; } c; c.f = v; return c.u; }
__device__ __forceinline__ float2 u2f(u64 u) { union { float2 f; u64 u; } c; c.u = u; return c.f; }
__device__ __forceinline__ u64 pack2(float lo, float hi) { float2 v; v.x = lo; v.y = hi; return f2u(v); }
__device__ __forceinline__ u64 fma2(u64 a, u64 b, u64 c) {
    u64 d; asm("fma.rn.f32x2 %0,%1,%2,%3;" : "=l"(d) : "l"(a), "l"(b), "l"(c)); return d;
}
__device__ __forceinline__ u64 mul2(u64 a, u64 b) {
    u64 d; asm("mul.rn.f32x2 %0,%1,%2;" : "=l"(d) : "l"(a), "l"(b)); return d;
}
__device__ __forceinline__ u64 add2(u64 a, u64 b) {
    u64 d; asm("add.rn.f32x2 %0,%1,%2;" : "=l"(d) : "l"(a), "l"(b)); return d;
}
__device__ __forceinline__ float ex2f(float x) {
    float y; asm("ex2.approx.f32 %0,%1;" : "=f"(y) : "f"(x)); return y;
}
__device__ __forceinline__ float wsum(float v) {
#pragma unroll
    for (int o = 16; o; o >>= 1) v += __shfl_xor_sync(0xffffffffu, v, o);
    return v;
}
__device__ __forceinline__ float wmax(float v) {
#pragma unroll
    for (int o = 16; o; o >>= 1) v = fmaxf(v, __shfl_xor_sync(0xffffffffu, v, o));
    return v;
}
__device__ __forceinline__ void cp16(uint32_t dst, const void* src) {
    asm volatile("cp.async.cg.shared.global [%0], [%1], 16;" :: "r"(dst), "l"(src));
}
#define CP_COMMIT() asm volatile("cp.async.commit_group;")
#define CP_WAIT(N)  asm volatile("cp.async.wait_group %0;" :: "n"(N))

__device__ __forceinline__ uint32_t h2pack(float a, float b) {
    __half2 h = __floats2half2_rn(a, b);
    return *(uint32_t*)&h;
}
__device__ __forceinline__ uint16_t h1(float a) {
    __half h = __float2half_rn(a);
    return *(uint16_t*)&h;
}
// m16n8k16 row.col f32 = f16 x f16 + f32
__device__ __forceinline__ void mma16816(float* d, const uint32_t* a, const uint32_t* b, const float* c) {
    asm volatile(
        "mma.sync.aligned.m16n8k16.row.col.f32.f16.f16.f32 "
        "{%0,%1,%2,%3}, {%4,%5,%6,%7}, {%8,%9}, {%10,%11,%12,%13};"
        : "=f"(d[0]), "=f"(d[1]), "=f"(d[2]), "=f"(d[3])
        : "r"(a[0]), "r"(a[1]), "r"(a[2]), "r"(a[3]), "r"(b[0]), "r"(b[1]),
          "f"(c[0]), "f"(c[1]), "f"(c[2]), "f"(c[3]));
}

// ---------------- QKV projection ----------------
__global__ void __launch_bounds__(256, 1)
qkv_kernel(const float* __restrict__ x0, int use_x,
           const float* __restrict__ W, const float* __restrict__ b) {
    __shared__ float Ws[42 * 14], bs[42], hs[64 * 14];
    const float* hin = use_x ? x0 : g_h;
    const int t = threadIdx.x;
    const int rb = blockIdx.x * 64;
    for (int i = t; i < 588; i += 256) Ws[i] = W[i];
    if (t < 42) bs[t] = b[t];
    for (int i = t; i < 64 * 14; i += 256) hs[i] = hin[rb * DM + i];
    __syncthreads();
    const float scale = rsqrtf(14.0f) * 1.44269504f;
    for (int idx = t; idx < 64 * 42; idx += 256) {
        int r = idx / 42, c = idx % 42;
        float s = bs[c];
#pragma unroll
        for (int d = 0; d < 14; d++) s = fmaf(hs[r * 14 + d], Ws[c * 14 + d], s);
        int row = rb + r, dd = c % 14;
        if (c < 14)      g_q[row * DM + dd] = s * scale;
        else if (c < 28) g_k[row * DM + dd] = s;
        else             g_v[row * DM + dd] = s;
    }
}

// ---------------- prep: norms + f16 hi/lo K/V repack ----------------
__global__ void __launch_bounds__(256, 1)
prep_kernel() {
    __shared__ float sp[8];
    const int t = threadIdx.x, lane = t & 31, warp = t >> 5;
    int key = blockIdx.x * 256 + t;
    float qn = 0.f, kn = 0.f;
    float kv[14], vv[14];
#pragma unroll
    for (int d = 0; d < 14; d++) {
        float qf = g_q[key * DM + d]; qn = fmaf(qf, qf, qn);
        kv[d] = g_k[key * DM + d]; kn = fmaf(kv[d], kv[d], kn);
        vv[d] = g_v[key * DM + d];
    }
    g_qn[key] = sqrtf(qn);

    // K repack: arr0 = hi d0-7, arr1 = hi d8-13 + [1.0, 0], arr2 = lo d0-7, arr3 = lo d8-13 + [0,0]
    __half hi[16], lo[16];
#pragma unroll
    for (int d = 0; d < 14; d++) {
        hi[d] = __float2half_rn(kv[d]);
        lo[d] = __float2half_rn(kv[d] - __half2float(hi[d]));
    }
    hi[14] = __float2half_rn(1.0f); hi[15] = __float2half_rn(0.f);
    lo[14] = __float2half_rn(0.f);  lo[15] = __float2half_rn(0.f);
    {
        __half* p0 = g_kp + (0 * NROWS + key) * 8;
        __half* p1 = g_kp + (1 * NROWS + key) * 8;
        __half* p2 = g_kp + (2 * NROWS + key) * 8;
        __half* p3 = g_kp + (3 * NROWS + key) * 8;
#pragma unroll
        for (int d = 0; d < 8; d++) { p0[d] = hi[d]; p1[d] = hi[8 + d]; p2[d] = lo[d]; p3[d] = lo[8 + d]; }
    }
    // V transposed: rows 0-13 hi, 14 ones, 15 zero, 16-29 lo, 30-31 zero
#pragma unroll
    for (int d = 0; d < 14; d++) {
        __half vh = __float2half_rn(vv[d]);
        g_vt[d][key] = vh;
        g_vt[16 + d][key] = __float2half_rn(vv[d] - __half2float(vh));
    }
    g_vt[14][key] = __float2half_rn(1.0f);
    g_vt[15][key] = __float2half_rn(0.f);
    g_vt[30][key] = __float2half_rn(0.f);
    g_vt[31][key] = __float2half_rn(0.f);

    kn = wmax(kn);
    if (lane == 0) sp[warp] = kn;
    __syncthreads();
    if (t == 0) {
        float m = sp[0];
#pragma unroll
        for (int w = 1; w < 8; w++) m = fmaxf(m, sp[w]);
        g_kmaxpart[blockIdx.x] = m;
    }
}

// ---------------- mma.sync flash attention ----------------
// grid 128 = 64 q-tiles (128 q) x 2 key-halves; 256 thr = 8 warps x 16 queries.
// smem per buffer: K 4 arrays x 256 x 16B = 16384; Vt 32 rows x 528B = 16896.
#define KBUF 16384
#define BUFSTRIDE (16384 + 16896)
#define ATTN_SMEM (2 * BUFSTRIDE)
__device__ __forceinline__ void tile_cp2(uint32_t sbase, int buf, int key0c, int t) {
    uint32_t dst = sbase + (uint32_t)buf * BUFSTRIDE;
#pragma unroll
    for (int s = 0; s < 4; s++) {
        int i = t + s * 256;                    // 1024 K segs
        int a = i >> 8, key = i & 255;
        cp16(dst + (uint32_t)a * 4096 + (uint32_t)key * 16,
             g_kp + ((size_t)a * NROWS + key0c + key) * 8);
    }
#pragma unroll
    for (int s = 0; s < 4; s++) {
        int i = t + s * 256;                    // 1024 V segs
        int row = i >> 5, seg = i & 31;
        cp16(dst + KBUF + (uint32_t)row * 528 + (uint32_t)seg * 16,
             &g_vt[row][key0c + seg * 8]);
    }
}

__global__ void __launch_bounds__(256, 1)
attn_mma_kernel() {
    extern __shared__ char smc[];
    const int t = threadIdx.x, lane = t & 31, warp = t >> 5;
    const int g = lane >> 2, tg = lane & 3;
    const int tile = blockIdx.x >> 1, half = blockIdx.x & 1;
    const int key0 = half * 4096;
    const uint32_t sbase = (uint32_t)__cvta_generic_to_shared(smc);

    float mk2 = 0.f;
#pragma unroll
    for (int i = 0; i < 32; i++) mk2 = fmaxf(mk2, __ldg(g_kmaxpart + i));
    const float maxk = sqrtf(mk2);

    // Q fragments (hi/lo f16 split), bias in dim14 (hi+lo), dim15 = 0
    const int qbase = tile * 128 + warp * 16;
    uint32_t qhi[4], qlo[4];
    {
        int r0 = qbase + g, r1 = r0 + 8;
        float v0a = g_q[r0 * DM + 2 * tg],     v1a = g_q[r0 * DM + 2 * tg + 1];
        float v0b = g_q[r1 * DM + 2 * tg],     v1b = g_q[r1 * DM + 2 * tg + 1];
        float v2a, v3a, v2b, v3b;
        if (tg < 3) {
            v2a = g_q[r0 * DM + 8 + 2 * tg]; v3a = g_q[r0 * DM + 9 + 2 * tg];
            v2b = g_q[r1 * DM + 8 + 2 * tg]; v3b = g_q[r1 * DM + 9 + 2 * tg];
        } else {
            v2a = -__ldg(g_qn + r0) * maxk; v3a = 0.f;
            v2b = -__ldg(g_qn + r1) * maxk; v3b = 0.f;
        }
        float vals[4][2] = {{v0a, v1a}, {v0b, v1b}, {v2a, v3a}, {v2b, v3b}};
#pragma unroll
        for (int i = 0; i < 4; i++) {
            qhi[i] = h2pack(vals[i][0], vals[i][1]);
            __half2 hh = *(__half2*)&qhi[i];
            qlo[i] = h2pack(vals[i][0] - __low2float(hh), vals[i][1] - __high2float(hh));
        }
    }

    float O0[4] = {0.f, 0.f, 0.f, 0.f};
    float O1[4] = {0.f, 0.f, 0.f, 0.f};

    tile_cp2(sbase, 0, key0, t);
    CP_COMMIT();

    for (int c = 0; c < 16; c++) {
        if (c < 15) {
            tile_cp2(sbase, (c + 1) & 1, key0 + (c + 1) * 256, t);
            CP_COMMIT();
            CP_WAIT(1);
        } else {
            CP_WAIT(0);
        }
        __syncthreads();

        const char* kb = smc + (c & 1) * BUFSTRIDE;
        const char* vb = kb + KBUF;

        for (int j = 0; j < 256; j += 16) {
            // K fragments (conflict-free: word = 4g+tg)
            const char* k0 = kb + (size_t)(j + g) * 16 + tg * 4;
            const char* k1 = kb + (size_t)(j + 8 + g) * 16 + tg * 4;
            uint32_t bh0[2] = { *(const uint32_t*)k0,          *(const uint32_t*)(k0 + 4096) };
            uint32_t bl0[2] = { *(const uint32_t*)(k0 + 8192), *(const uint32_t*)(k0 + 12288) };
            uint32_t bh1[2] = { *(const uint32_t*)k1,          *(const uint32_t*)(k1 + 4096) };
            uint32_t bl1[2] = { *(const uint32_t*)(k1 + 8192), *(const uint32_t*)(k1 + 12288) };

            float S0[4] = {0.f, 0.f, 0.f, 0.f}, S1[4] = {0.f, 0.f, 0.f, 0.f};
            mma16816(S0, qhi, bh0, S0);
            mma16816(S0, qhi, bl0, S0);
            mma16816(S0, qlo, bh0, S0);
            mma16816(S1, qhi, bh1, S1);
            mma16816(S1, qhi, bl1, S1);
            mma16816(S1, qlo, bh1, S1);

            float p[8];
#pragma unroll
            for (int i = 0; i < 4; i++) { p[i] = ex2f(S0[i]); p[4 + i] = ex2f(S1[i]); }
            uint32_t phi[4], plo[4];
#pragma unroll
            for (int i = 0; i < 4; i++) {
                phi[i] = h2pack(p[2 * i], p[2 * i + 1]);
                __half2 hh = *(__half2*)&phi[i];
                plo[i] = h2pack(p[2 * i] - __low2float(hh), p[2 * i + 1] - __high2float(hh));
            }

            // V fragments (rows: g hi-dims0-7, 8+g hi-dims8-15(incl l), 16+g lo, 24+g lo)
            const char* v0 = vb + (size_t)((j >> 1) + tg) * 4;
            uint32_t vh0[2] = { *(const uint32_t*)(v0 + (size_t)g * 528),
                                *(const uint32_t*)(v0 + (size_t)g * 528 + 16) };
            uint32_t vh1[2] = { *(const uint32_t*)(v0 + (size_t)(8 + g) * 528),
                                *(const uint32_t*)(v0 + (size_t)(8 + g) * 528 + 16) };
            uint32_t vl0[2] = { *(const uint32_t*)(v0 + (size_t)(16 + g) * 528),
                                *(const uint32_t*)(v0 + (size_t)(16 + g) * 528 + 16) };
            uint32_t vl1[2] = { *(const uint32_t*)(v0 + (size_t)(24 + g) * 528),
                                *(const uint32_t*)(v0 + (size_t)(24 + g) * 528 + 16) };

            mma16816(O0, phi, vh0, O0);
            mma16816(O1, phi, vh1, O1);
            mma16816(O0, plo, vh0, O0);
            mma16816(O1, plo, vh1, O1);
            mma16816(O0, phi, vl0, O0);
            mma16816(O1, phi, vl1, O1);
        }
        __syncthreads();
    }

    // write partials: row r dims [0..13] = o, dim14 = l
    {
        int r0 = qbase + g;
        float* d0 = g_part + ((size_t)half * NROWS + r0) * 16;
        float* d1 = g_part + ((size_t)half * NROWS + r0 + 8) * 16;
        *(float2*)(d0 + 2 * tg)     = make_float2(O0[0], O0[1]);
        *(float2*)(d0 + 8 + 2 * tg) = make_float2(O1[0], O1[1]);
        *(float2*)(d1 + 2 * tg)     = make_float2(O0[2], O0[3]);
        *(float2*)(d1 + 8 + 2 * tg) = make_float2(O1[2], O1[3]);
    }
}

// ---------------- combine: merge halves + out-proj + residual + LN1 ----------------
__global__ void __launch_bounds__(256, 1)
combine_kernel(const float* __restrict__ x0, int use_x,
               const float* __restrict__ Wo, const float* __restrict__ bo,
               const float* __restrict__ lng, const float* __restrict__ lnb) {
    __shared__ float wos[196], bos[14];
    const int t = threadIdx.x;
    if (t < 196) wos[t] = Wo[t];
    if (t < 14)  bos[t] = bo[t];
    __syncthreads();
    const float* hin = use_x ? x0 : g_h;
    int row = blockIdx.x * 256 + t;
    const float* p0 = g_part + (size_t)row * 16;
    const float* p1 = g_part + ((size_t)NROWS + row) * 16;
    float inv = 1.f / (p0[14] + p1[14]);
    float a[14];
#pragma unroll
    for (int d = 0; d < 14; d++) a[d] = (p0[d] + p1[d]) * inv;
    float pre[14], mu = 0.f;
#pragma unroll
    for (int d2 = 0; d2 < 14; d2++) {
        float ov = bos[d2];
#pragma unroll
        for (int d = 0; d < 14; d++) ov = fmaf(a[d], wos[d2 * 14 + d], ov);
        ov += hin[row * DM + d2];
        pre[d2] = ov; mu += ov;
    }
    mu *= (1.f / 14.f);
    float var = 0.f;
#pragma unroll
    for (int d = 0; d < 14; d++) { float z = pre[d] - mu; var = fmaf(z, z, var); }
    float rs = rsqrtf(var * (1.f / 14.f) + EPS);
#pragma unroll
    for (int d = 0; d < 14; d++)
        g_h[row * DM + d] = (pre[d] - mu) * rs * __ldg(lng + d) + __ldg(lnb + d);
}

// ---------------- FFN (14->2048->14) + residual + LN2, dp-major conflict-free ----
__global__ void __launch_bounds__(256, 1)
ffn_kernel(const float* __restrict__ W1, const float* __restrict__ b1,
           const float* __restrict__ W2, const float* __restrict__ b2,
           const float* __restrict__ lng, const float* __restrict__ lnb) {
    extern __shared__ float sm[];
    float2* W1s = (float2*)sm;          // [dp*2048+j]
    float2* W2p = W1s + 14336;          // [dp*2048+j] = (W2[2dp][j], W2[2dp+1][j])
    const int t = threadIdx.x, lane = t & 31, warp = t >> 5;
    {
        const float2* W1g = (const float2*)W1;
        for (int i = t; i < 14336; i += 256) {
            int dp = i >> 11, j = i & 2047;
            W1s[i] = W1g[j * 7 + dp];
            float2 v;
            v.x = __ldg(W2 + (2 * dp) * 2048 + j);
            v.y = __ldg(W2 + (2 * dp + 1) * 2048 + j);
            W2p[i] = v;
        }
    }
    __syncthreads();

    const int rbase = blockIdx.x * 64;
    for (int s = 0; s < 2; s++) {
        const int r0 = rbase + (s * 8 + warp) * 4;
        u64 hB[4][7];
#pragma unroll
        for (int r = 0; r < 4; r++) {
            const float2* hp = ((const float2*)g_h) + (r0 + r) * 7;
#pragma unroll
            for (int dp = 0; dp < 7; dp++) hB[r][dp] = f2u(__ldg(hp + dp));
        }
        u64 acc[7][4];
#pragma unroll
        for (int dp = 0; dp < 7; dp++)
#pragma unroll
            for (int r = 0; r < 4; r++) acc[dp][r] = 0ull;

        for (int it = 0; it < 64; it++) {
            const int j = it * 32 + lane;
            const float b1j = __ldg(b1 + j);
            u64 s2[4];
            {
                u64 w = f2u(W1s[j]);
#pragma unroll
                for (int r = 0; r < 4; r++) s2[r] = mul2(hB[r][0], w);
            }
#pragma unroll
            for (int dp = 1; dp < 7; dp++) {
                u64 w = f2u(W1s[dp * 2048 + j]);
#pragma unroll
                for (int r = 0; r < 4; r++) s2[r] = fma2(hB[r][dp], w, s2[r]);
            }
            u64 hd[4];
#pragma unroll
            for (int r = 0; r < 4; r++) {
                float2 sf = u2f(s2[r]);
                float hj = fmaxf(sf.x + sf.y + b1j, 0.f);
                hd[r] = pack2(hj, hj);
            }
#pragma unroll
            for (int dp = 0; dp < 7; dp++) {
                u64 w = f2u(W2p[dp * 2048 + j]);
#pragma unroll
                for (int r = 0; r < 4; r++) acc[dp][r] = fma2(hd[r], w, acc[dp][r]);
            }
        }
#pragma unroll
        for (int off = 16; off; off >>= 1)
#pragma unroll
            for (int dp = 0; dp < 7; dp++)
#pragma unroll
                for (int r = 0; r < 4; r++)
                    acc[dp][r] = add2(acc[dp][r], __shfl_xor_sync(0xffffffffu, acc[dp][r], off));

#pragma unroll
        for (int r = 0; r < 4; r++) {
            if (lane == r) {
                float pre[14], mu = 0.f;
#pragma unroll
                for (int dp = 0; dp < 7; dp++) {
                    float2 a = u2f(acc[dp][r]);
                    float2 h2 = u2f(hB[r][dp]);
                    float p0 = a.x + __ldg(b2 + 2 * dp) + h2.x;
                    float p1 = a.y + __ldg(b2 + 2 * dp + 1) + h2.y;
                    pre[2 * dp] = p0; pre[2 * dp + 1] = p1;
                    mu += p0 + p1;
                }
                mu *= (1.f / 14.f);
                float var = 0.f;
#pragma unroll
                for (int d = 0; d < 14; d++) { float z = pre[d] - mu; var = fmaf(z, z, var); }
                float rs = rsqrtf(var * (1.f / 14.f) + EPS);
                float* hw = g_h + (r0 + r) * DM;
#pragma unroll
                for (int d = 0; d < 14; d++)
                    hw[d] = (pre[d] - mu) * rs * __ldg(lng + d) + __ldg(lnb + d);
            }
        }
    }
}

// ---------------- head 1 ----------------
__global__ void __launch_bounds__(256, 1)
head1_kernel(const float* __restrict__ w1, const float* __restrict__ b1f,
             const float* __restrict__ w2, const float* __restrict__ b2f,
             float* __restrict__ out) {
    int n = blockIdx.x * 256 + threadIdx.x;
    float h[14];
#pragma unroll
    for (int d = 0; d < 14; d++) h[d] = g_h[n * DM + d];
    float size = __ldg(b2f);
#pragma unroll
    for (int d2 = 0; d2 < 14; d2++) {
        float s = __ldg(b1f + d2);
#pragma unroll
        for (int d = 0; d < 14; d++) s = fmaf(h[d], __ldg(w1 + d2 * 14 + d), s);
        size = fmaf(s, __ldg(w2 + d2), size);
    }
    out[n] = size;
    g_sizef[n] = (float)(int)size;
}

// ---------------- head 2 ----------------
__global__ void __launch_bounds__(256, 1)
head2_kernel(const float* __restrict__ x, const float* __restrict__ y,
             const float* __restrict__ w3, const float* __restrict__ b3,
             const float* __restrict__ w4, const float* __restrict__ b4,
             const float* __restrict__ w5, const float* __restrict__ b5,
             float* __restrict__ out) {
    extern __shared__ float sm[];
    float* w3s = sm;             // 13056
    float* ins = w3s + 13056;    // 816
    float* red = ins + 816;      // 128
    float* r1f = red + 128;      // 4608
    float* w4s = r1f + 4608;     // 16640
    const int t = threadIdx.x, lane = t & 31, warp = t >> 5;
    const int rbase = blockIdx.x * 16;
    for (int i = t; i < 13056; i += 256) w3s[i] = w3[i];
    for (int i = t; i < 16 * 51; i += 256) {
        int r = i / 51, c = i % 51, row = rbase + r;
        float v;
        if (c == 0)      v = g_sizef[row];
        else if (c < 15) v = x[row * DM + c - 1];
        else             v = y[row * MF + c - 15];
        ins[i] = v;
    }
    __syncthreads();

    float r1a[16];
    float b3t = __ldg(b3 + t);
#pragma unroll
    for (int r = 0; r < 16; r++) r1a[r] = b3t;
    for (int i = 0; i < 51; i++) {
        float w = w3s[t * 51 + i];
#pragma unroll
        for (int r = 0; r < 16; r++) r1a[r] = fmaf(ins[r * 51 + i], w, r1a[r]);
    }
#pragma unroll
    for (int rp = 0; rp < 8; rp++) {
        float2 v;
        v.x = fmaxf(r1a[2 * rp], 0.f);
        v.y = fmaxf(r1a[2 * rp + 1], 0.f);
        ((float2*)r1f)[t * 9 + rp] = v;
    }
    __syncthreads();

    u64 r2a2[8];
    float b4t = __ldg(b4 + t);
#pragma unroll
    for (int rp = 0; rp < 8; rp++) r2a2[rp] = pack2(b4t, b4t);
    for (int c = 0; c < 4; c++) {
        for (int i = t; i < 256 * 64; i += 256) {
            int o = i >> 6, jj = i & 63;
            w4s[o * 65 + jj] = __ldg(w4 + o * 256 + c * 64 + jj);
        }
        __syncthreads();
#pragma unroll 4
        for (int jj = 0; jj < 64; jj++) {
            float w = w4s[t * 65 + jj];
            u64 w2p = pack2(w, w);
            const float2* rp1 = ((const float2*)r1f) + (c * 64 + jj) * 9;
#pragma unroll
            for (int rp = 0; rp < 8; rp++) r2a2[rp] = fma2(f2u(rp1[rp]), w2p, r2a2[rp]);
        }
        __syncthreads();
    }

    float w5t = __ldg(w5 + t);
#pragma unroll
    for (int rp = 0; rp < 8; rp++) {
        float2 f = u2f(r2a2[rp]);
        float v0 = wsum(fmaxf(f.x, 0.f) * w5t);
        float v1 = wsum(fmaxf(f.y, 0.f) * w5t);
        if (lane == 0) {
            red[warp * 16 + 2 * rp] = v0;
            red[warp * 16 + 2 * rp + 1] = v1;
        }
    }
    __syncthreads();
    if (t < 16) {
        float s = __ldg(b5);
        for (int w = 0; w < 8; w++) s += red[w * 16 + t];
        int row = rbase + t;
        out[NROWS + row] = (g_sizef[row] != 0.f) ? s : 0.f;
    }
}

// ---------------- launcher ----------------
extern "C" void kernel_launch(void* const* d_in, const int* in_sizes, int n_in,
                              void* d_out, int out_size) {
    const float* x    = (const float*)d_in[0];
    const float* y    = (const float*)d_in[1];
    const float* wqkv = (const float*)d_in[2];
    const float* bqkv = (const float*)d_in[3];
    const float* wo   = (const float*)d_in[4];
    const float* bo   = (const float*)d_in[5];
    const float* ln1g = (const float*)d_in[6];
    const float* ln1b = (const float*)d_in[7];
    const float* ffw1 = (const float*)d_in[8];
    const float* ffb1 = (const float*)d_in[9];
    const float* ffw2 = (const float*)d_in[10];
    const float* ffb2 = (const float*)d_in[11];
    const float* ln2g = (const float*)d_in[12];
    const float* ln2b = (const float*)d_in[13];
    const float* fc1w = (const float*)d_in[14];
    const float* fc1b = (const float*)d_in[15];
    const float* fc2w = (const float*)d_in[16];
    const float* fc2b = (const float*)d_in[17];
    const float* fc3w = (const float*)d_in[18];
    const float* fc3b = (const float*)d_in[19];
    const float* fc4w = (const float*)d_in[20];
    const float* fc4b = (const float*)d_in[21];
    const float* fc5w = (const float*)d_in[22];
    const float* fc5b = (const float*)d_in[23];
    float* out = (float*)d_out;

    const int ffn_smem = 14336 * 2 * 8;
    const int h2_smem  = (13056 + 816 + 128 + 4608 + 16640) * (int)sizeof(float);
    cudaFuncSetAttribute(attn_mma_kernel, cudaFuncAttributeMaxDynamicSharedMemorySize, ATTN_SMEM);
    cudaFuncSetAttribute(ffn_kernel,      cudaFuncAttributeMaxDynamicSharedMemorySize, ffn_smem);
    cudaFuncSetAttribute(head2_kernel,    cudaFuncAttributeMaxDynamicSharedMemorySize, h2_smem);

    for (int l = 0; l < 2; l++) {
        qkv_kernel<<<128, 256>>>(x, (l == 0) ? 1 : 0, wqkv + l * 588, bqkv + l * 42);
        prep_kernel<<<32, 256>>>();
        attn_mma_kernel<<<128, 256, ATTN_SMEM>>>();
        combine_kernel<<<32, 256>>>(x, (l == 0) ? 1 : 0, wo + l * 196, bo + l * 14,
                                    ln1g + l * 14, ln1b + l * 14);
        ffn_kernel<<<128, 256, ffn_smem>>>(ffw1 + l * 28672, ffb1 + l * 2048,
                                           ffw2 + l * 28672, ffb2 + l * 14,
                                           ln2g + l * 14, ln2b + l * 14);
    }
    head1_kernel<<<32, 256>>>(fc1w, fc1b, fc2w, fc2b, out);
    head2_kernel<<<512, 256, h2_smem>>>(x, y, fc3w, fc3b, fc4w, fc4b, fc5w, fc5b, out);
}

// round 8
// speedup vs baseline: 1.9231x; 1.1929x over previous
#include <cuda_runtime.h>
#include <cuda_fp16.h>
#include <stdint.h>

#define NROWS 8192
#define DM 14
#define MF 36
#define EPS 1e-5f
typedef unsigned long long u64;

__device__ __align__(16) float g_h[NROWS * DM];
__device__ __align__(16) float g_q[NROWS * DM];   // pre-scaled by D^-0.5*log2(e)
__device__ __align__(16) float g_k[NROWS * DM];
__device__ __align__(16) float g_v[NROWS * DM];
__device__ __align__(16) float g_part[2 * NROWS * 16];
__device__ __align__(16) __half g_kp[4 * NROWS * 8];  // [arr][key][8] f16
__device__ __align__(16) __half g_vt[32][NROWS];      // [dim-ish][key] f16
__device__ __align__(16) __half g_w1p[4 * 2048 * 8];  // FFN W1 repack [arr][j][8]
__device__ __align__(16) __half g_w2p[32 * 2048];     // FFN W2t repack [row][j]
__device__ float g_sizef[NROWS];
__device__ float g_qn[NROWS];
__device__ float g_kmaxpart[32];

// ---- f32x2 helpers ----
__device__ __forceinline__ u64 f2u(float2 v) { union { float2 f; u64 u; } c; c.f = v; return c.u; }
__device__ __forceinline__ float2 u2f(u64 u) { union { float2 f; u64 u; } c; c.u = u; return c.f; }
__device__ __forceinline__ u64 pack2(float lo, float hi) { float2 v; v.x = lo; v.y = hi; return f2u(v); }
__device__ __forceinline__ u64 fma2(u64 a, u64 b, u64 c) {
    u64 d; asm("fma.rn.f32x2 %0,%1,%2,%3;" : "=l"(d) : "l"(a), "l"(b), "l"(c)); return d;
}
__device__ __forceinline__ float ex2f(float x) {
    float y; asm("ex2.approx.f32 %0,%1;" : "=f"(y) : "f"(x)); return y;
}
__device__ __forceinline__ float wsum(float v) {
#pragma unroll
    for (int o = 16; o; o >>= 1) v += __shfl_xor_sync(0xffffffffu, v, o);
    return v;
}
__device__ __forceinline__ float wmax(float v) {
#pragma unroll
    for (int o = 16; o; o >>= 1) v = fmaxf(v, __shfl_xor_sync(0xffffffffu, v, o));
    return v;
}
__device__ __forceinline__ void cp16(uint32_t dst, const void* src) {
    asm volatile("cp.async.cg.shared.global [%0], [%1], 16;" :: "r"(dst), "l"(src));
}
#define CP_COMMIT() asm volatile("cp.async.commit_group;")
#define CP_WAIT(N)  asm volatile("cp.async.wait_group %0;" :: "n"(N))

__device__ __forceinline__ uint32_t h2pack(float a, float b) {
    __half2 h = __floats2half2_rn(a, b);
    return *(uint32_t*)&h;
}
__device__ __forceinline__ void mma16816(float* d, const uint32_t* a, const uint32_t* b, const float* c) {
    asm volatile(
        "mma.sync.aligned.m16n8k16.row.col.f32.f16.f16.f32 "
        "{%0,%1,%2,%3}, {%4,%5,%6,%7}, {%8,%9}, {%10,%11,%12,%13};"
        : "=f"(d[0]), "=f"(d[1]), "=f"(d[2]), "=f"(d[3])
        : "r"(a[0]), "r"(a[1]), "r"(a[2]), "r"(a[3]), "r"(b[0]), "r"(b[1]),
          "f"(c[0]), "f"(c[1]), "f"(c[2]), "f"(c[3]));
}

// ---------------- QKV projection ----------------
__global__ void __launch_bounds__(256, 1)
qkv_kernel(const float* __restrict__ x0, int use_x,
           const float* __restrict__ W, const float* __restrict__ b) {
    __shared__ float Ws[42 * 14], bs[42], hs[64 * 14];
    const float* hin = use_x ? x0 : g_h;
    const int t = threadIdx.x;
    const int rb = blockIdx.x * 64;
    for (int i = t; i < 588; i += 256) Ws[i] = W[i];
    if (t < 42) bs[t] = b[t];
    for (int i = t; i < 64 * 14; i += 256) hs[i] = hin[rb * DM + i];
    __syncthreads();
    const float scale = rsqrtf(14.0f) * 1.44269504f;
    for (int idx = t; idx < 64 * 42; idx += 256) {
        int r = idx / 42, c = idx % 42;
        float s = bs[c];
#pragma unroll
        for (int d = 0; d < 14; d++) s = fmaf(hs[r * 14 + d], Ws[c * 14 + d], s);
        int row = rb + r, dd = c % 14;
        if (c < 14)      g_q[row * DM + dd] = s * scale;
        else if (c < 28) g_k[row * DM + dd] = s;
        else             g_v[row * DM + dd] = s;
    }
}

// ---------------- prep: norms + f16 hi/lo K/V repack ----------------
__global__ void __launch_bounds__(256, 1)
prep_kernel() {
    __shared__ float sp[8];
    const int t = threadIdx.x, lane = t & 31, warp = t >> 5;
    int key = blockIdx.x * 256 + t;
    float qn = 0.f, kn = 0.f;
    float kv[14], vv[14];
#pragma unroll
    for (int d = 0; d < 14; d++) {
        float qf = g_q[key * DM + d]; qn = fmaf(qf, qf, qn);
        kv[d] = g_k[key * DM + d]; kn = fmaf(kv[d], kv[d], kn);
        vv[d] = g_v[key * DM + d];
    }
    g_qn[key] = sqrtf(qn);

    __half hi[16], lo[16];
#pragma unroll
    for (int d = 0; d < 14; d++) {
        hi[d] = __float2half_rn(kv[d]);
        lo[d] = __float2half_rn(kv[d] - __half2float(hi[d]));
    }
    hi[14] = __float2half_rn(1.0f); hi[15] = __float2half_rn(0.f);
    lo[14] = __float2half_rn(0.f);  lo[15] = __float2half_rn(0.f);
    {
        __half* p0 = g_kp + (0 * NROWS + key) * 8;
        __half* p1 = g_kp + (1 * NROWS + key) * 8;
        __half* p2 = g_kp + (2 * NROWS + key) * 8;
        __half* p3 = g_kp + (3 * NROWS + key) * 8;
#pragma unroll
        for (int d = 0; d < 8; d++) { p0[d] = hi[d]; p1[d] = hi[8 + d]; p2[d] = lo[d]; p3[d] = lo[8 + d]; }
    }
#pragma unroll
    for (int d = 0; d < 14; d++) {
        __half vh = __float2half_rn(vv[d]);
        g_vt[d][key] = vh;
        g_vt[16 + d][key] = __float2half_rn(vv[d] - __half2float(vh));
    }
    g_vt[14][key] = __float2half_rn(1.0f);
    g_vt[15][key] = __float2half_rn(0.f);
    g_vt[30][key] = __float2half_rn(0.f);
    g_vt[31][key] = __float2half_rn(0.f);

    kn = wmax(kn);
    if (lane == 0) sp[warp] = kn;
    __syncthreads();
    if (t == 0) {
        float m = sp[0];
#pragma unroll
        for (int w = 1; w < 8; w++) m = fmaxf(m, sp[w]);
        g_kmaxpart[blockIdx.x] = m;
    }
}

// ---------------- mma.sync flash attention (512 thr, warp-groups split keys) ----
// grid 128 = 64 q-tiles (128 q) x 2 key-halves. 16 warps: w8 = queries, wg = key half.
#define KBUF 16384
#define BUFSTRIDE (16384 + 16896)
#define ATTN_SMEM (2 * BUFSTRIDE)
__device__ __forceinline__ void tile_cp2(uint32_t sbase, int buf, int key0c, int t) {
    uint32_t dst = sbase + (uint32_t)buf * BUFSTRIDE;
#pragma unroll
    for (int s = 0; s < 2; s++) {
        int i = t + s * 512;                    // 1024 K segs
        int a = i >> 8, key = i & 255;
        cp16(dst + (uint32_t)a * 4096 + (uint32_t)key * 16,
             g_kp + ((size_t)a * NROWS + key0c + key) * 8);
    }
#pragma unroll
    for (int s = 0; s < 2; s++) {
        int i = t + s * 512;                    // 1024 V segs
        int row = i >> 5, seg = i & 31;
        cp16(dst + KBUF + (uint32_t)row * 528 + (uint32_t)seg * 16,
             &g_vt[row][key0c + seg * 8]);
    }
}

__global__ void __launch_bounds__(512, 1)
attn_mma_kernel() {
    extern __shared__ char smc[];
    const int t = threadIdx.x, lane = t & 31, warp = t >> 5;
    const int g = lane >> 2, tg = lane & 3;
    const int w8 = warp & 7, wg = warp >> 3;
    const int tile = blockIdx.x >> 1, half = blockIdx.x & 1;
    const int key0 = half * 4096;
    const uint32_t sbase = (uint32_t)__cvta_generic_to_shared(smc);

    float mk2 = 0.f;
#pragma unroll
    for (int i = 0; i < 32; i++) mk2 = fmaxf(mk2, __ldg(g_kmaxpart + i));
    const float maxk = sqrtf(mk2);

    const int qbase = tile * 128 + w8 * 16;
    uint32_t qhi[4], qlo[4];
    {
        int r0 = qbase + g, r1 = r0 + 8;
        float v0a = g_q[r0 * DM + 2 * tg],     v1a = g_q[r0 * DM + 2 * tg + 1];
        float v0b = g_q[r1 * DM + 2 * tg],     v1b = g_q[r1 * DM + 2 * tg + 1];
        float v2a, v3a, v2b, v3b;
        if (tg < 3) {
            v2a = g_q[r0 * DM + 8 + 2 * tg]; v3a = g_q[r0 * DM + 9 + 2 * tg];
            v2b = g_q[r1 * DM + 8 + 2 * tg]; v3b = g_q[r1 * DM + 9 + 2 * tg];
        } else {
            v2a = -__ldg(g_qn + r0) * maxk; v3a = 0.f;
            v2b = -__ldg(g_qn + r1) * maxk; v3b = 0.f;
        }
        float vals[4][2] = {{v0a, v1a}, {v0b, v1b}, {v2a, v3a}, {v2b, v3b}};
#pragma unroll
        for (int i = 0; i < 4; i++) {
            qhi[i] = h2pack(vals[i][0], vals[i][1]);
            __half2 hh = *(__half2*)&qhi[i];
            qlo[i] = h2pack(vals[i][0] - __low2float(hh), vals[i][1] - __high2float(hh));
        }
    }

    float O0[4] = {0.f, 0.f, 0.f, 0.f};
    float O1[4] = {0.f, 0.f, 0.f, 0.f};

    tile_cp2(sbase, 0, key0, t);
    CP_COMMIT();

    for (int c = 0; c < 16; c++) {
        if (c < 15) {
            tile_cp2(sbase, (c + 1) & 1, key0 + (c + 1) * 256, t);
            CP_COMMIT();
            CP_WAIT(1);
        } else {
            CP_WAIT(0);
        }
        __syncthreads();

        const char* kb = smc + (c & 1) * BUFSTRIDE;
        const char* vb = kb + KBUF;

        for (int step = 0; step < 8; step++) {
            const int j = wg * 128 + step * 16;
            const char* k0 = kb + (size_t)(j + g) * 16 + tg * 4;
            const char* k1 = kb + (size_t)(j + 8 + g) * 16 + tg * 4;
            uint32_t bh0[2] = { *(const uint32_t*)k0,          *(const uint32_t*)(k0 + 4096) };
            uint32_t bl0[2] = { *(const uint32_t*)(k0 + 8192), *(const uint32_t*)(k0 + 12288) };
            uint32_t bh1[2] = { *(const uint32_t*)k1,          *(const uint32_t*)(k1 + 4096) };
            uint32_t bl1[2] = { *(const uint32_t*)(k1 + 8192), *(const uint32_t*)(k1 + 12288) };

            float S0[4] = {0.f, 0.f, 0.f, 0.f}, S1[4] = {0.f, 0.f, 0.f, 0.f};
            mma16816(S0, qhi, bh0, S0);
            mma16816(S0, qhi, bl0, S0);
            mma16816(S0, qlo, bh0, S0);
            mma16816(S1, qhi, bh1, S1);
            mma16816(S1, qhi, bl1, S1);
            mma16816(S1, qlo, bh1, S1);

            float p[8];
#pragma unroll
            for (int i = 0; i < 4; i++) { p[i] = ex2f(S0[i]); p[4 + i] = ex2f(S1[i]); }
            uint32_t phi[4], plo[4];
#pragma unroll
            for (int i = 0; i < 4; i++) {
                phi[i] = h2pack(p[2 * i], p[2 * i + 1]);
                __half2 hh = *(__half2*)&phi[i];
                plo[i] = h2pack(p[2 * i] - __low2float(hh), p[2 * i + 1] - __high2float(hh));
            }

            const char* v0 = vb + (size_t)(j * 2 + tg * 4);
            uint32_t vh0[2] = { *(const uint32_t*)(v0 + (size_t)g * 528),
                                *(const uint32_t*)(v0 + (size_t)g * 528 + 16) };
            uint32_t vh1[2] = { *(const uint32_t*)(v0 + (size_t)(8 + g) * 528),
                                *(const uint32_t*)(v0 + (size_t)(8 + g) * 528 + 16) };
            uint32_t vl0[2] = { *(const uint32_t*)(v0 + (size_t)(16 + g) * 528),
                                *(const uint32_t*)(v0 + (size_t)(16 + g) * 528 + 16) };
            uint32_t vl1[2] = { *(const uint32_t*)(v0 + (size_t)(24 + g) * 528),
                                *(const uint32_t*)(v0 + (size_t)(24 + g) * 528 + 16) };

            mma16816(O0, phi, vh0, O0);
            mma16816(O1, phi, vh1, O1);
            mma16816(O0, plo, vh0, O0);
            mma16816(O1, plo, vh1, O1);
            mma16816(O0, phi, vl0, O0);
            mma16816(O1, phi, vl1, O1);
        }
        __syncthreads();
    }

    // merge the two warp-groups via smem, then write partials
    {
        float* osum = (float*)smc;           // 128 x 16 floats (buffers dead now)
        int lr = w8 * 16 + g;
        if (wg == 0) {
            osum[lr * 16 + 2 * tg]           = O0[0];
            osum[lr * 16 + 2 * tg + 1]       = O0[1];
            osum[lr * 16 + 8 + 2 * tg]       = O1[0];
            osum[lr * 16 + 9 + 2 * tg]       = O1[1];
            osum[(lr + 8) * 16 + 2 * tg]     = O0[2];
            osum[(lr + 8) * 16 + 2 * tg + 1] = O0[3];
            osum[(lr + 8) * 16 + 8 + 2 * tg] = O1[2];
            osum[(lr + 8) * 16 + 9 + 2 * tg] = O1[3];
        }
        __syncthreads();
        if (wg == 1) {
            osum[lr * 16 + 2 * tg]           += O0[0];
            osum[lr * 16 + 2 * tg + 1]       += O0[1];
            osum[lr * 16 + 8 + 2 * tg]       += O1[0];
            osum[lr * 16 + 9 + 2 * tg]       += O1[1];
            osum[(lr + 8) * 16 + 2 * tg]     += O0[2];
            osum[(lr + 8) * 16 + 2 * tg + 1] += O0[3];
            osum[(lr + 8) * 16 + 8 + 2 * tg] += O1[2];
            osum[(lr + 8) * 16 + 9 + 2 * tg] += O1[3];
        }
        __syncthreads();
        float4 v = ((const float4*)osum)[t];
        int row = t >> 2, seg = t & 3;
        *(float4*)(g_part + ((size_t)half * NROWS + tile * 128 + row) * 16 + seg * 4) = v;
    }
}

// ---------------- combine: merge halves + out-proj + residual + LN1 ----------------
__global__ void __launch_bounds__(256, 1)
combine_kernel(const float* __restrict__ x0, int use_x,
               const float* __restrict__ Wo, const float* __restrict__ bo,
               const float* __restrict__ lng, const float* __restrict__ lnb) {
    __shared__ float wos[196], bos[14];
    const int t = threadIdx.x;
    if (t < 196) wos[t] = Wo[t];
    if (t < 14)  bos[t] = bo[t];
    __syncthreads();
    const float* hin = use_x ? x0 : g_h;
    int row = blockIdx.x * 256 + t;
    const float* p0 = g_part + (size_t)row * 16;
    const float* p1 = g_part + ((size_t)NROWS + row) * 16;
    float inv = 1.f / (p0[14] + p1[14]);
    float a[14];
#pragma unroll
    for (int d = 0; d < 14; d++) a[d] = (p0[d] + p1[d]) * inv;
    float pre[14], mu = 0.f;
#pragma unroll
    for (int d2 = 0; d2 < 14; d2++) {
        float ov = bos[d2];
#pragma unroll
        for (int d = 0; d < 14; d++) ov = fmaf(a[d], wos[d2 * 14 + d], ov);
        ov += hin[row * DM + d2];
        pre[d2] = ov; mu += ov;
    }
    mu *= (1.f / 14.f);
    float var = 0.f;
#pragma unroll
    for (int d = 0; d < 14; d++) { float z = pre[d] - mu; var = fmaf(z, z, var); }
    float rs = rsqrtf(var * (1.f / 14.f) + EPS);
#pragma unroll
    for (int d = 0; d < 14; d++)
        g_h[row * DM + d] = (pre[d] - mu) * rs * __ldg(lng + d) + __ldg(lnb + d);
}

// ---------------- wprep: repack FFN weights to f16 hi/lo MMA layouts ----------------
__global__ void __launch_bounds__(256, 1)
wprep_kernel(const float* __restrict__ W1, const float* __restrict__ b1,
             const float* __restrict__ W2) {
    int j = blockIdx.x * 256 + threadIdx.x;   // 0..2047
    __half hi[16], lo[16];
#pragma unroll
    for (int d = 0; d < 14; d++) {
        float w = W1[j * 14 + d];
        hi[d] = __float2half_rn(w);
        lo[d] = __float2half_rn(w - __half2float(hi[d]));
    }
    {
        float bb = __ldg(b1 + j);
        hi[14] = __float2half_rn(bb);
        lo[14] = __float2half_rn(bb - __half2float(hi[14]));
        hi[15] = __float2half_rn(0.f); lo[15] = __float2half_rn(0.f);
    }
    {
        __half* p0 = g_w1p + (0 * 2048 + j) * 8;
        __half* p1 = g_w1p + (1 * 2048 + j) * 8;
        __half* p2 = g_w1p + (2 * 2048 + j) * 8;
        __half* p3 = g_w1p + (3 * 2048 + j) * 8;
#pragma unroll
        for (int d = 0; d < 8; d++) { p0[d] = hi[d]; p1[d] = hi[8 + d]; p2[d] = lo[d]; p3[d] = lo[8 + d]; }
    }
#pragma unroll
    for (int d = 0; d < 14; d++) {
        float w = W2[d * 2048 + j];
        __half wh = __float2half_rn(w);
        g_w2p[d * 2048 + j] = wh;
        g_w2p[(16 + d) * 2048 + j] = __float2half_rn(w - __half2float(wh));
    }
    g_w2p[14 * 2048 + j] = __float2half_rn(0.f);
    g_w2p[15 * 2048 + j] = __float2half_rn(0.f);
    g_w2p[30 * 2048 + j] = __float2half_rn(0.f);
    g_w2p[31 * 2048 + j] = __float2half_rn(0.f);
}

// ---------------- FFN via mma.sync: GEMM1 + relu + GEMM2 + residual + LN2 ----------
// grid 128 x 256 thr: 64 rows/CTA; warps: rw = row quarter (m16), jh = hidden half.
#define FW1B 16384                 // 4 arrays x 256 j x 16B
#define FBUF (FW1B + 16896)        // + 32 rows x 528B
#define FFN_SMEM (2 * FBUF)
__device__ __forceinline__ void ffn_cp(uint32_t sbase, int buf, int chunk, int t) {
    uint32_t dst = sbase + (uint32_t)buf * FBUF;
#pragma unroll
    for (int s = 0; s < 4; s++) {
        int i = t + s * 256;                    // 1024 W1 segs
        int a = i >> 8, j = i & 255;
        cp16(dst + (uint32_t)a * 4096 + (uint32_t)j * 16,
             g_w1p + ((size_t)a * 2048 + chunk * 256 + j) * 8);
    }
#pragma unroll
    for (int s = 0; s < 4; s++) {
        int i = t + s * 256;                    // 1024 W2 segs
        int row = i >> 5, seg = i & 31;
        cp16(dst + FW1B + (uint32_t)row * 528 + (uint32_t)seg * 16,
             g_w2p + (size_t)row * 2048 + chunk * 256 + seg * 8);
    }
}

__global__ void __launch_bounds__(256, 1)
ffn_mma_kernel(const float* __restrict__ b2,
               const float* __restrict__ lng, const float* __restrict__ lnb) {
    extern __shared__ char smc[];
    const int t = threadIdx.x, lane = t & 31, warp = t >> 5;
    const int g = lane >> 2, tg = lane & 3;
    const int rw = warp & 3, jh = warp >> 2;
    const uint32_t sbase = (uint32_t)__cvta_generic_to_shared(smc);
    const int rbase = blockIdx.x * 64 + rw * 16;

    // h fragments (hi/lo), col14 = 1.0 pairs with b1 in W1 col14
    uint32_t qhi[4], qlo[4];
    {
        int r0 = rbase + g, r1 = r0 + 8;
        float v0a = g_h[r0 * DM + 2 * tg],     v1a = g_h[r0 * DM + 2 * tg + 1];
        float v0b = g_h[r1 * DM + 2 * tg],     v1b = g_h[r1 * DM + 2 * tg + 1];
        float v2a, v3a, v2b, v3b;
        if (tg < 3) {
            v2a = g_h[r0 * DM + 8 + 2 * tg]; v3a = g_h[r0 * DM + 9 + 2 * tg];
            v2b = g_h[r1 * DM + 8 + 2 * tg]; v3b = g_h[r1 * DM + 9 + 2 * tg];
        } else {
            v2a = 1.0f; v3a = 0.f;
            v2b = 1.0f; v3b = 0.f;
        }
        float vals[4][2] = {{v0a, v1a}, {v0b, v1b}, {v2a, v3a}, {v2b, v3b}};
#pragma unroll
        for (int i = 0; i < 4; i++) {
            qhi[i] = h2pack(vals[i][0], vals[i][1]);
            __half2 hh = *(__half2*)&qhi[i];
            qlo[i] = h2pack(vals[i][0] - __low2float(hh), vals[i][1] - __high2float(hh));
        }
    }

    float O0[4] = {0.f, 0.f, 0.f, 0.f};
    float O1[4] = {0.f, 0.f, 0.f, 0.f};

    ffn_cp(sbase, 0, 0, t);
    CP_COMMIT();

    for (int c = 0; c < 8; c++) {
        if (c < 7) {
            ffn_cp(sbase, (c + 1) & 1, c + 1, t);
            CP_COMMIT();
            CP_WAIT(1);
        } else {
            CP_WAIT(0);
        }
        __syncthreads();

        const char* kb = smc + (c & 1) * FBUF;
        const char* vb = kb + FW1B;

        for (int step = 0; step < 8; step++) {
            const int j = jh * 128 + step * 16;
            const char* k0 = kb + (size_t)(j + g) * 16 + tg * 4;
            const char* k1 = kb + (size_t)(j + 8 + g) * 16 + tg * 4;
            uint32_t bh0[2] = { *(const uint32_t*)k0,          *(const uint32_t*)(k0 + 4096) };
            uint32_t bl0[2] = { *(const uint32_t*)(k0 + 8192), *(const uint32_t*)(k0 + 12288) };
            uint32_t bh1[2] = { *(const uint32_t*)k1,          *(const uint32_t*)(k1 + 4096) };
            uint32_t bl1[2] = { *(const uint32_t*)(k1 + 8192), *(const uint32_t*)(k1 + 12288) };

            float S0[4] = {0.f, 0.f, 0.f, 0.f}, S1[4] = {0.f, 0.f, 0.f, 0.f};
            mma16816(S0, qhi, bh0, S0);
            mma16816(S0, qhi, bl0, S0);
            mma16816(S0, qlo, bh0, S0);
            mma16816(S1, qhi, bh1, S1);
            mma16816(S1, qhi, bl1, S1);
            mma16816(S1, qlo, bh1, S1);

            float p[8];
#pragma unroll
            for (int i = 0; i < 4; i++) { p[i] = fmaxf(S0[i], 0.f); p[4 + i] = fmaxf(S1[i], 0.f); }
            uint32_t phi[4], plo[4];
#pragma unroll
            for (int i = 0; i < 4; i++) {
                phi[i] = h2pack(p[2 * i], p[2 * i + 1]);
                __half2 hh = *(__half2*)&phi[i];
                plo[i] = h2pack(p[2 * i] - __low2float(hh), p[2 * i + 1] - __high2float(hh));
            }

            const char* v0 = vb + (size_t)(j * 2 + tg * 4);
            uint32_t vh0[2] = { *(const uint32_t*)(v0 + (size_t)g * 528),
                                *(const uint32_t*)(v0 + (size_t)g * 528 + 16) };
            uint32_t vh1[2] = { *(const uint32_t*)(v0 + (size_t)(8 + g) * 528),
                                *(const uint32_t*)(v0 + (size_t)(8 + g) * 528 + 16) };
            uint32_t vl0[2] = { *(const uint32_t*)(v0 + (size_t)(16 + g) * 528),
                                *(const uint32_t*)(v0 + (size_t)(16 + g) * 528 + 16) };
            uint32_t vl1[2] = { *(const uint32_t*)(v0 + (size_t)(24 + g) * 528),
                                *(const uint32_t*)(v0 + (size_t)(24 + g) * 528 + 16) };

            mma16816(O0, phi, vh0, O0);
            mma16816(O1, phi, vh1, O1);
            mma16816(O0, plo, vh0, O0);
            mma16816(O1, plo, vh1, O1);
            mma16816(O0, phi, vl0, O0);
            mma16816(O1, phi, vl1, O1);
        }
        __syncthreads();
    }

    // merge jh groups via smem, then LN epilogue
    {
        float* osum = (float*)smc;        // 64 x 16 floats
        int lr = rw * 16 + g;
        if (jh == 0) {
            osum[lr * 16 + 2 * tg]           = O0[0];
            osum[lr * 16 + 2 * tg + 1]       = O0[1];
            osum[lr * 16 + 8 + 2 * tg]       = O1[0];
            osum[lr * 16 + 9 + 2 * tg]       = O1[1];
            osum[(lr + 8) * 16 + 2 * tg]     = O0[2];
            osum[(lr + 8) * 16 + 2 * tg + 1] = O0[3];
            osum[(lr + 8) * 16 + 8 + 2 * tg] = O1[2];
            osum[(lr + 8) * 16 + 9 + 2 * tg] = O1[3];
        }
        __syncthreads();
        if (jh == 1) {
            osum[lr * 16 + 2 * tg]           += O0[0];
            osum[lr * 16 + 2 * tg + 1]       += O0[1];
            osum[lr * 16 + 8 + 2 * tg]       += O1[0];
            osum[lr * 16 + 9 + 2 * tg]       += O1[1];
            osum[(lr + 8) * 16 + 2 * tg]     += O0[2];
            osum[(lr + 8) * 16 + 2 * tg + 1] += O0[3];
            osum[(lr + 8) * 16 + 8 + 2 * tg] += O1[2];
            osum[(lr + 8) * 16 + 9 + 2 * tg] += O1[3];
        }
        __syncthreads();
        if (t < 64) {
            int row = blockIdx.x * 64 + t;
            float pre[14], mu = 0.f;
#pragma unroll
            for (int d = 0; d < 14; d++) {
                float v = osum[t * 16 + d] + __ldg(b2 + d) + g_h[row * DM + d];
                pre[d] = v; mu += v;
            }
            mu *= (1.f / 14.f);
            float var = 0.f;
#pragma unroll
            for (int d = 0; d < 14; d++) { float z = pre[d] - mu; var = fmaf(z, z, var); }
            float rs = rsqrtf(var * (1.f / 14.f) + EPS);
#pragma unroll
            for (int d = 0; d < 14; d++)
                g_h[row * DM + d] = (pre[d] - mu) * rs * __ldg(lng + d) + __ldg(lnb + d);
        }
    }
}

// ---------------- head 1 ----------------
__global__ void __launch_bounds__(256, 1)
head1_kernel(const float* __restrict__ w1, const float* __restrict__ b1f,
             const float* __restrict__ w2, const float* __restrict__ b2f,
             float* __restrict__ out) {
    int n = blockIdx.x * 256 + threadIdx.x;
    float h[14];
#pragma unroll
    for (int d = 0; d < 14; d++) h[d] = g_h[n * DM + d];
    float size = __ldg(b2f);
#pragma unroll
    for (int d2 = 0; d2 < 14; d2++) {
        float s = __ldg(b1f + d2);
#pragma unroll
        for (int d = 0; d < 14; d++) s = fmaf(h[d], __ldg(w1 + d2 * 14 + d), s);
        size = fmaf(s, __ldg(w2 + d2), size);
    }
    out[n] = size;
    g_sizef[n] = (float)(int)size;
}

// ---------------- head 2 ----------------
__device__ __forceinline__ u64 pack2b(float lo, float hi) { float2 v; v.x = lo; v.y = hi; return f2u(v); }
__global__ void __launch_bounds__(256, 1)
head2_kernel(const float* __restrict__ x, const float* __restrict__ y,
             const float* __restrict__ w3, const float* __restrict__ b3,
             const float* __restrict__ w4, const float* __restrict__ b4,
             const float* __restrict__ w5, const float* __restrict__ b5,
             float* __restrict__ out) {
    extern __shared__ float sm[];
    float* w3s = sm;             // 13056
    float* ins = w3s + 13056;    // 816
    float* red = ins + 816;      // 128
    float* r1f = red + 128;      // 4608
    float* w4s = r1f + 4608;     // 16640
    const int t = threadIdx.x, lane = t & 31, warp = t >> 5;
    const int rbase = blockIdx.x * 16;
    for (int i = t; i < 13056; i += 256) w3s[i] = w3[i];
    for (int i = t; i < 16 * 51; i += 256) {
        int r = i / 51, c = i % 51, row = rbase + r;
        float v;
        if (c == 0)      v = g_sizef[row];
        else if (c < 15) v = x[row * DM + c - 1];
        else             v = y[row * MF + c - 15];
        ins[i] = v;
    }
    __syncthreads();

    float r1a[16];
    float b3t = __ldg(b3 + t);
#pragma unroll
    for (int r = 0; r < 16; r++) r1a[r] = b3t;
    for (int i = 0; i < 51; i++) {
        float w = w3s[t * 51 + i];
#pragma unroll
        for (int r = 0; r < 16; r++) r1a[r] = fmaf(ins[r * 51 + i], w, r1a[r]);
    }
#pragma unroll
    for (int rp = 0; rp < 8; rp++) {
        float2 v;
        v.x = fmaxf(r1a[2 * rp], 0.f);
        v.y = fmaxf(r1a[2 * rp + 1], 0.f);
        ((float2*)r1f)[t * 9 + rp] = v;
    }
    __syncthreads();

    u64 r2a2[8];
    float b4t = __ldg(b4 + t);
#pragma unroll
    for (int rp = 0; rp < 8; rp++) r2a2[rp] = pack2b(b4t, b4t);
    for (int c = 0; c < 4; c++) {
        for (int i = t; i < 256 * 64; i += 256) {
            int o = i >> 6, jj = i & 63;
            w4s[o * 65 + jj] = __ldg(w4 + o * 256 + c * 64 + jj);
        }
        __syncthreads();
#pragma unroll 4
        for (int jj = 0; jj < 64; jj++) {
            float w = w4s[t * 65 + jj];
            u64 w2p = pack2b(w, w);
            const float2* rp1 = ((const float2*)r1f) + (c * 64 + jj) * 9;
#pragma unroll
            for (int rp = 0; rp < 8; rp++) r2a2[rp] = fma2(f2u(rp1[rp]), w2p, r2a2[rp]);
        }
        __syncthreads();
    }

    float w5t = __ldg(w5 + t);
#pragma unroll
    for (int rp = 0; rp < 8; rp++) {
        float2 f = u2f(r2a2[rp]);
        float v0 = wsum(fmaxf(f.x, 0.f) * w5t);
        float v1 = wsum(fmaxf(f.y, 0.f) * w5t);
        if (lane == 0) {
            red[warp * 16 + 2 * rp] = v0;
            red[warp * 16 + 2 * rp + 1] = v1;
        }
    }
    __syncthreads();
    if (t < 16) {
        float s = __ldg(b5);
        for (int w = 0; w < 8; w++) s += red[w * 16 + t];
        int row = rbase + t;
        out[NROWS + row] = (g_sizef[row] != 0.f) ? s : 0.f;
    }
}

// ---------------- launcher ----------------
extern "C" void kernel_launch(void* const* d_in, const int* in_sizes, int n_in,
                              void* d_out, int out_size) {
    const float* x    = (const float*)d_in[0];
    const float* y    = (const float*)d_in[1];
    const float* wqkv = (const float*)d_in[2];
    const float* bqkv = (const float*)d_in[3];
    const float* wo   = (const float*)d_in[4];
    const float* bo   = (const float*)d_in[5];
    const float* ln1g = (const float*)d_in[6];
    const float* ln1b = (const float*)d_in[7];
    const float* ffw1 = (const float*)d_in[8];
    const float* ffb1 = (const float*)d_in[9];
    const float* ffw2 = (const float*)d_in[10];
    const float* ffb2 = (const float*)d_in[11];
    const float* ln2g = (const float*)d_in[12];
    const float* ln2b = (const float*)d_in[13];
    const float* fc1w = (const float*)d_in[14];
    const float* fc1b = (const float*)d_in[15];
    const float* fc2w = (const float*)d_in[16];
    const float* fc2b = (const float*)d_in[17];
    const float* fc3w = (const float*)d_in[18];
    const float* fc3b = (const float*)d_in[19];
    const float* fc4w = (const float*)d_in[20];
    const float* fc4b = (const float*)d_in[21];
    const float* fc5w = (const float*)d_in[22];
    const float* fc5b = (const float*)d_in[23];
    float* out = (float*)d_out;

    const int h2_smem = (13056 + 816 + 128 + 4608 + 16640) * (int)sizeof(float);
    cudaFuncSetAttribute(attn_mma_kernel, cudaFuncAttributeMaxDynamicSharedMemorySize, ATTN_SMEM);
    cudaFuncSetAttribute(ffn_mma_kernel,  cudaFuncAttributeMaxDynamicSharedMemorySize, FFN_SMEM);
    cudaFuncSetAttribute(head2_kernel,    cudaFuncAttributeMaxDynamicSharedMemorySize, h2_smem);

    for (int l = 0; l < 2; l++) {
        qkv_kernel<<<128, 256>>>(x, (l == 0) ? 1 : 0, wqkv + l * 588, bqkv + l * 42);
        prep_kernel<<<32, 256>>>();
        wprep_kernel<<<8, 256>>>(ffw1 + l * 28672, ffb1 + l * 2048, ffw2 + l * 28672);
        attn_mma_kernel<<<128, 512, ATTN_SMEM>>>();
        combine_kernel<<<32, 256>>>(x, (l == 0) ? 1 : 0, wo + l * 196, bo + l * 14,
                                    ln1g + l * 14, ln1b + l * 14);
        ffn_mma_kernel<<<128, 256, FFN_SMEM>>>(ffb2 + l * 14, ln2g + l * 14, ln2b + l * 14);
    }
    head1_kernel<<<32, 256>>>(fc1w, fc1b, fc2w, fc2b, out);
    head2_kernel<<<512, 256, h2_smem>>>(x, y, fc3w, fc3b, fc4w, fc4b, fc5w, fc5b, out);
}

// round 9
// speedup vs baseline: 1.9939x; 1.0368x over previous
#include <cuda_runtime.h>
#include <cuda_fp16.h>
#include <stdint.h>

#define NROWS 8192
#define DM 14
#define MF 36
#define EPS 1e-5f
typedef unsigned long long u64;

__device__ __align__(16) float g_h[NROWS * DM];
__device__ __align__(16) float g_q[NROWS * DM];   // pre-scaled by D^-0.5*log2(e)
__device__ __align__(16) float g_part[8 * NROWS * 16];
__device__ __align__(16) __half g_kp[4 * NROWS * 8];   // [arr][key][8] f16
__device__ __align__(16) __half g_vt[32][NROWS];       // [dim-ish][key] f16
__device__ __align__(16) __half g_w1p[2 * 4 * 2048 * 8];  // per-layer W1 repack
__device__ __align__(16) __half g_w2p[2 * 32 * 2048];     // per-layer W2t repack
__device__ float g_sizef[NROWS];
__device__ float g_qn[NROWS];
__device__ float g_kmaxpart[128];

// ---- helpers ----
__device__ __forceinline__ u64 f2u(float2 v) { union { float2 f; u64 u; } c; c.f = v; return c.u; }
__device__ __forceinline__ float2 u2f(u64 u) { union { float2 f; u64 u; } c; c.u = u; return c.f; }
__device__ __forceinline__ u64 pack2(float lo, float hi) { float2 v; v.x = lo; v.y = hi; return f2u(v); }
__device__ __forceinline__ u64 fma2(u64 a, u64 b, u64 c) {
    u64 d; asm("fma.rn.f32x2 %0,%1,%2,%3;" : "=l"(d) : "l"(a), "l"(b), "l"(c)); return d;
}
__device__ __forceinline__ float ex2f(float x) {
    float y; asm("ex2.approx.f32 %0,%1;" : "=f"(y) : "f"(x)); return y;
}
__device__ __forceinline__ float wsum(float v) {
#pragma unroll
    for (int o = 16; o; o >>= 1) v += __shfl_xor_sync(0xffffffffu, v, o);
    return v;
}
__device__ __forceinline__ float wmax(float v) {
#pragma unroll
    for (int o = 16; o; o >>= 1) v = fmaxf(v, __shfl_xor_sync(0xffffffffu, v, o));
    return v;
}
__device__ __forceinline__ void cp16(uint32_t dst, const void* src) {
    asm volatile("cp.async.cg.shared.global [%0], [%1], 16;" :: "r"(dst), "l"(src));
}
#define CP_COMMIT() asm volatile("cp.async.commit_group;")
#define CP_WAIT(N)  asm volatile("cp.async.wait_group %0;" :: "n"(N))

__device__ __forceinline__ uint32_t h2pack(float a, float b) {
    __half2 h = __floats2half2_rn(a, b);
    return *(uint32_t*)&h;
}
__device__ __forceinline__ void mma16816(float* d, const uint32_t* a, const uint32_t* b, const float* c) {
    asm volatile(
        "mma.sync.aligned.m16n8k16.row.col.f32.f16.f16.f32 "
        "{%0,%1,%2,%3}, {%4,%5,%6,%7}, {%8,%9}, {%10,%11,%12,%13};"
        : "=f"(d[0]), "=f"(d[1]), "=f"(d[2]), "=f"(d[3])
        : "r"(a[0]), "r"(a[1]), "r"(a[2]), "r"(a[3]), "r"(b[0]), "r"(b[1]),
          "f"(c[0]), "f"(c[1]), "f"(c[2]), "f"(c[3]));
}

// ---------------- fused QKV projection + prep ----------------
// 128 CTAs x 256 thr; 64 rows each. Computes qkv into smem, then per-row:
// q (scaled) -> g_q, |q| -> g_qn, K/V f16 hi/lo repack -> g_kp/g_vt, kmax partial.
#define QS 49
__global__ void __launch_bounds__(256, 1)
qkv_prep_kernel(const float* __restrict__ x0, int use_x,
                const float* __restrict__ W, const float* __restrict__ b) {
    __shared__ float Ws[42 * 14], bs[42], hs[64 * 14], qkvs[64 * QS], sp[2];
    const float* hin = use_x ? x0 : g_h;
    const int t = threadIdx.x;
    const int rb = blockIdx.x * 64;
    for (int i = t; i < 588; i += 256) Ws[i] = W[i];
    if (t < 42) bs[t] = b[t];
    for (int i = t; i < 64 * 14; i += 256) hs[i] = hin[rb * DM + i];
    __syncthreads();
    const float scale = rsqrtf(14.0f) * 1.44269504f;
    for (int idx = t; idx < 64 * 42; idx += 256) {
        int r = idx / 42, c = idx % 42;
        float s = bs[c];
#pragma unroll
        for (int d = 0; d < 14; d++) s = fmaf(hs[r * 14 + d], Ws[c * 14 + d], s);
        qkvs[r * QS + c] = (c < 14) ? s * scale : s;
    }
    __syncthreads();

    if (t < 64) {
        int row = rb + t;
        const float* qr = qkvs + t * QS;
        float qn = 0.f, kn = 0.f;
        float kv[14], vv[14];
#pragma unroll
        for (int d = 0; d < 14; d++) {
            float qf = qr[d];
            g_q[row * DM + d] = qf;
            qn = fmaf(qf, qf, qn);
            kv[d] = qr[14 + d]; kn = fmaf(kv[d], kv[d], kn);
            vv[d] = qr[28 + d];
        }
        g_qn[row] = sqrtf(qn);

        __half hi[16], lo[16];
#pragma unroll
        for (int d = 0; d < 14; d++) {
            hi[d] = __float2half_rn(kv[d]);
            lo[d] = __float2half_rn(kv[d] - __half2float(hi[d]));
        }
        hi[14] = __float2half_rn(1.0f); hi[15] = __float2half_rn(0.f);
        lo[14] = __float2half_rn(0.f);  lo[15] = __float2half_rn(0.f);
        {
            __half* p0 = g_kp + (0 * NROWS + row) * 8;
            __half* p1 = g_kp + (1 * NROWS + row) * 8;
            __half* p2 = g_kp + (2 * NROWS + row) * 8;
            __half* p3 = g_kp + (3 * NROWS + row) * 8;
#pragma unroll
            for (int d = 0; d < 8; d++) { p0[d] = hi[d]; p1[d] = hi[8 + d]; p2[d] = lo[d]; p3[d] = lo[8 + d]; }
        }
#pragma unroll
        for (int d = 0; d < 14; d++) {
            __half vh = __float2half_rn(vv[d]);
            g_vt[d][row] = vh;
            g_vt[16 + d][row] = __float2half_rn(vv[d] - __half2float(vh));
        }
        g_vt[14][row] = __float2half_rn(1.0f);
        g_vt[15][row] = __float2half_rn(0.f);
        g_vt[30][row] = __float2half_rn(0.f);
        g_vt[31][row] = __float2half_rn(0.f);

        kn = wmax(kn);                      // warps 0,1 fully active for t<64
        if ((t & 31) == 0) sp[t >> 5] = kn;
    }
    __syncthreads();
    if (t == 0) g_kmaxpart[blockIdx.x] = fmaxf(sp[0], sp[1]);
}

// ---------------- mma.sync flash attention, 8-way key split ----------------
// grid 512 = 64 q-tiles x 8 key-parts; 256 thr = 8 warps x 16 queries; 3 CTAs/SM.
#define KBUF 16384
#define BUFSTRIDE (16384 + 16896)
#define ATTN_SMEM (2 * BUFSTRIDE)
__device__ __forceinline__ void tile_cp2(uint32_t sbase, int buf, int key0c, int t) {
    uint32_t dst = sbase + (uint32_t)buf * BUFSTRIDE;
#pragma unroll
    for (int s = 0; s < 4; s++) {
        int i = t + s * 256;                    // 1024 K segs
        int a = i >> 8, key = i & 255;
        cp16(dst + (uint32_t)a * 4096 + (uint32_t)key * 16,
             g_kp + ((size_t)a * NROWS + key0c + key) * 8);
    }
#pragma unroll
    for (int s = 0; s < 4; s++) {
        int i = t + s * 256;                    // 1024 V segs
        int row = i >> 5, seg = i & 31;
        cp16(dst + KBUF + (uint32_t)row * 528 + (uint32_t)seg * 16,
             &g_vt[row][key0c + seg * 8]);
    }
}

__global__ void __launch_bounds__(256, 3)
attn_mma_kernel() {
    extern __shared__ char smc[];
    const int t = threadIdx.x, lane = t & 31, warp = t >> 5;
    const int g = lane >> 2, tg = lane & 3;
    const int tile = blockIdx.x >> 3, part = blockIdx.x & 7;
    const int key0 = part * 1024;
    const uint32_t sbase = (uint32_t)__cvta_generic_to_shared(smc);

    float mk2 = 0.f;
    for (int i = lane; i < 128; i += 32) mk2 = fmaxf(mk2, __ldg(g_kmaxpart + i));
    mk2 = wmax(mk2);
    const float maxk = sqrtf(mk2);

    const int qbase = tile * 128 + warp * 16;
    uint32_t qhi[4], qlo[4];
    {
        int r0 = qbase + g, r1 = r0 + 8;
        float v0a = g_q[r0 * DM + 2 * tg],     v1a = g_q[r0 * DM + 2 * tg + 1];
        float v0b = g_q[r1 * DM + 2 * tg],     v1b = g_q[r1 * DM + 2 * tg + 1];
        float v2a, v3a, v2b, v3b;
        if (tg < 3) {
            v2a = g_q[r0 * DM + 8 + 2 * tg]; v3a = g_q[r0 * DM + 9 + 2 * tg];
            v2b = g_q[r1 * DM + 8 + 2 * tg]; v3b = g_q[r1 * DM + 9 + 2 * tg];
        } else {
            v2a = -__ldg(g_qn + r0) * maxk; v3a = 0.f;
            v2b = -__ldg(g_qn + r1) * maxk; v3b = 0.f;
        }
        float vals[4][2] = {{v0a, v1a}, {v0b, v1b}, {v2a, v3a}, {v2b, v3b}};
#pragma unroll
        for (int i = 0; i < 4; i++) {
            qhi[i] = h2pack(vals[i][0], vals[i][1]);
            __half2 hh = *(__half2*)&qhi[i];
            qlo[i] = h2pack(vals[i][0] - __low2float(hh), vals[i][1] - __high2float(hh));
        }
    }

    float O0[4] = {0.f, 0.f, 0.f, 0.f};
    float O1[4] = {0.f, 0.f, 0.f, 0.f};

    tile_cp2(sbase, 0, key0, t);
    CP_COMMIT();

    for (int c = 0; c < 4; c++) {
        if (c < 3) {
            tile_cp2(sbase, (c + 1) & 1, key0 + (c + 1) * 256, t);
            CP_COMMIT();
            CP_WAIT(1);
        } else {
            CP_WAIT(0);
        }
        __syncthreads();

        const char* kb = smc + (c & 1) * BUFSTRIDE;
        const char* vb = kb + KBUF;

        for (int j = 0; j < 256; j += 16) {
            const char* k0 = kb + (size_t)(j + g) * 16 + tg * 4;
            const char* k1 = kb + (size_t)(j + 8 + g) * 16 + tg * 4;
            uint32_t bh0[2] = { *(const uint32_t*)k0,          *(const uint32_t*)(k0 + 4096) };
            uint32_t bl0[2] = { *(const uint32_t*)(k0 + 8192), *(const uint32_t*)(k0 + 12288) };
            uint32_t bh1[2] = { *(const uint32_t*)k1,          *(const uint32_t*)(k1 + 4096) };
            uint32_t bl1[2] = { *(const uint32_t*)(k1 + 8192), *(const uint32_t*)(k1 + 12288) };

            float S0[4] = {0.f, 0.f, 0.f, 0.f}, S1[4] = {0.f, 0.f, 0.f, 0.f};
            mma16816(S0, qhi, bh0, S0);
            mma16816(S0, qhi, bl0, S0);
            mma16816(S0, qlo, bh0, S0);
            mma16816(S1, qhi, bh1, S1);
            mma16816(S1, qhi, bl1, S1);
            mma16816(S1, qlo, bh1, S1);

            float p[8];
#pragma unroll
            for (int i = 0; i < 4; i++) { p[i] = ex2f(S0[i]); p[4 + i] = ex2f(S1[i]); }
            uint32_t phi[4], plo[4];
#pragma unroll
            for (int i = 0; i < 4; i++) {
                phi[i] = h2pack(p[2 * i], p[2 * i + 1]);
                __half2 hh = *(__half2*)&phi[i];
                plo[i] = h2pack(p[2 * i] - __low2float(hh), p[2 * i + 1] - __high2float(hh));
            }

            const char* v0 = vb + (size_t)(j * 2 + tg * 4);
            uint32_t vh0[2] = { *(const uint32_t*)(v0 + (size_t)g * 528),
                                *(const uint32_t*)(v0 + (size_t)g * 528 + 16) };
            uint32_t vh1[2] = { *(const uint32_t*)(v0 + (size_t)(8 + g) * 528),
                                *(const uint32_t*)(v0 + (size_t)(8 + g) * 528 + 16) };
            uint32_t vl0[2] = { *(const uint32_t*)(v0 + (size_t)(16 + g) * 528),
                                *(const uint32_t*)(v0 + (size_t)(16 + g) * 528 + 16) };
            uint32_t vl1[2] = { *(const uint32_t*)(v0 + (size_t)(24 + g) * 528),
                                *(const uint32_t*)(v0 + (size_t)(24 + g) * 528 + 16) };

            mma16816(O0, phi, vh0, O0);
            mma16816(O1, phi, vh1, O1);
            mma16816(O0, plo, vh0, O0);
            mma16816(O1, plo, vh1, O1);
            mma16816(O0, phi, vl0, O0);
            mma16816(O1, phi, vl1, O1);
        }
        __syncthreads();
    }

    // write partials
    {
        int r0 = qbase + g;
        float* d0 = g_part + ((size_t)part * NROWS + r0) * 16;
        float* d1 = g_part + ((size_t)part * NROWS + r0 + 8) * 16;
        *(float2*)(d0 + 2 * tg)     = make_float2(O0[0], O0[1]);
        *(float2*)(d0 + 8 + 2 * tg) = make_float2(O1[0], O1[1]);
        *(float2*)(d1 + 2 * tg)     = make_float2(O0[2], O0[3]);
        *(float2*)(d1 + 8 + 2 * tg) = make_float2(O1[2], O1[3]);
    }
}

// ---------------- combine: merge 8 parts + out-proj + residual + LN1 ----------------
__global__ void __launch_bounds__(128, 1)
combine_kernel(const float* __restrict__ x0, int use_x,
               const float* __restrict__ Wo, const float* __restrict__ bo,
               const float* __restrict__ lng, const float* __restrict__ lnb) {
    __shared__ float wos[196], bos[14];
    const int t = threadIdx.x;
    for (int i = t; i < 196; i += 128) wos[i] = Wo[i];
    if (t < 14) bos[t] = bo[t];
    __syncthreads();
    const float* hin = use_x ? x0 : g_h;
    int row = blockIdx.x * 128 + t;
    float acc[16];
#pragma unroll
    for (int i = 0; i < 16; i++) acc[i] = 0.f;
#pragma unroll
    for (int pp = 0; pp < 8; pp++) {
        const float4* p = (const float4*)(g_part + ((size_t)pp * NROWS + row) * 16);
        float4 v0 = p[0], v1 = p[1], v2 = p[2], v3 = p[3];
        acc[0] += v0.x; acc[1] += v0.y; acc[2] += v0.z; acc[3] += v0.w;
        acc[4] += v1.x; acc[5] += v1.y; acc[6] += v1.z; acc[7] += v1.w;
        acc[8] += v2.x; acc[9] += v2.y; acc[10] += v2.z; acc[11] += v2.w;
        acc[12] += v3.x; acc[13] += v3.y; acc[14] += v3.z; acc[15] += v3.w;
    }
    float inv = 1.f / acc[14];
    float a[14];
#pragma unroll
    for (int d = 0; d < 14; d++) a[d] = acc[d] * inv;
    float pre[14], mu = 0.f;
#pragma unroll
    for (int d2 = 0; d2 < 14; d2++) {
        float ov = bos[d2];
#pragma unroll
        for (int d = 0; d < 14; d++) ov = fmaf(a[d], wos[d2 * 14 + d], ov);
        ov += hin[row * DM + d2];
        pre[d2] = ov; mu += ov;
    }
    mu *= (1.f / 14.f);
    float var = 0.f;
#pragma unroll
    for (int d = 0; d < 14; d++) { float z = pre[d] - mu; var = fmaf(z, z, var); }
    float rs = rsqrtf(var * (1.f / 14.f) + EPS);
#pragma unroll
    for (int d = 0; d < 14; d++)
        g_h[row * DM + d] = (pre[d] - mu) * rs * __ldg(lng + d) + __ldg(lnb + d);
}

// ---------------- wprep (both layers, once) ----------------
__global__ void __launch_bounds__(256, 1)
wprep_all_kernel(const float* __restrict__ W1a, const float* __restrict__ b1a,
                 const float* __restrict__ W2a) {
    int idx = blockIdx.x * 256 + threadIdx.x;   // 0..4095
    int layer = idx >> 11, j = idx & 2047;
    const float* W1 = W1a + layer * 28672;
    const float* b1 = b1a + layer * 2048;
    const float* W2 = W2a + layer * 28672;
    __half* w1p = g_w1p + layer * 65536;
    __half* w2p = g_w2p + layer * 65536;

    __half hi[16], lo[16];
#pragma unroll
    for (int d = 0; d < 14; d++) {
        float w = W1[j * 14 + d];
        hi[d] = __float2half_rn(w);
        lo[d] = __float2half_rn(w - __half2float(hi[d]));
    }
    {
        float bb = __ldg(b1 + j);
        hi[14] = __float2half_rn(bb);
        lo[14] = __float2half_rn(bb - __half2float(hi[14]));
        hi[15] = __float2half_rn(0.f); lo[15] = __float2half_rn(0.f);
    }
    {
        __half* p0 = w1p + (0 * 2048 + j) * 8;
        __half* p1 = w1p + (1 * 2048 + j) * 8;
        __half* p2 = w1p + (2 * 2048 + j) * 8;
        __half* p3 = w1p + (3 * 2048 + j) * 8;
#pragma unroll
        for (int d = 0; d < 8; d++) { p0[d] = hi[d]; p1[d] = hi[8 + d]; p2[d] = lo[d]; p3[d] = lo[8 + d]; }
    }
#pragma unroll
    for (int d = 0; d < 14; d++) {
        float w = W2[d * 2048 + j];
        __half wh = __float2half_rn(w);
        w2p[d * 2048 + j] = wh;
        w2p[(16 + d) * 2048 + j] = __float2half_rn(w - __half2float(wh));
    }
    w2p[14 * 2048 + j] = __float2half_rn(0.f);
    w2p[15 * 2048 + j] = __float2half_rn(0.f);
    w2p[30 * 2048 + j] = __float2half_rn(0.f);
    w2p[31 * 2048 + j] = __float2half_rn(0.f);
}

// ---------------- FFN via mma.sync, 32 rows/CTA, 4-way hidden split ----------------
#define FW1B 16384
#define FBUF (FW1B + 16896)
#define FFN_SMEM (2 * FBUF)
__device__ __forceinline__ void ffn_cp(uint32_t sbase, int buf, int chunk, int t, int layer) {
    uint32_t dst = sbase + (uint32_t)buf * FBUF;
    const __half* w1p = g_w1p + layer * 65536;
    const __half* w2p = g_w2p + layer * 65536;
#pragma unroll
    for (int s = 0; s < 4; s++) {
        int i = t + s * 256;
        int a = i >> 8, j = i & 255;
        cp16(dst + (uint32_t)a * 4096 + (uint32_t)j * 16,
             w1p + ((size_t)a * 2048 + chunk * 256 + j) * 8);
    }
#pragma unroll
    for (int s = 0; s < 4; s++) {
        int i = t + s * 256;
        int row = i >> 5, seg = i & 31;
        cp16(dst + FW1B + (uint32_t)row * 528 + (uint32_t)seg * 16,
             w2p + (size_t)row * 2048 + chunk * 256 + seg * 8);
    }
}

__global__ void __launch_bounds__(256, 2)
ffn_mma_kernel(int layer, const float* __restrict__ b2,
               const float* __restrict__ lng, const float* __restrict__ lnb) {
    extern __shared__ char smc[];
    const int t = threadIdx.x, lane = t & 31, warp = t >> 5;
    const int g = lane >> 2, tg = lane & 3;
    const int rw = warp & 1, jq = warp >> 1;
    const uint32_t sbase = (uint32_t)__cvta_generic_to_shared(smc);
    const int rbase = blockIdx.x * 32 + rw * 16;

    uint32_t qhi[4], qlo[4];
    {
        int r0 = rbase + g, r1 = r0 + 8;
        float v0a = g_h[r0 * DM + 2 * tg],     v1a = g_h[r0 * DM + 2 * tg + 1];
        float v0b = g_h[r1 * DM + 2 * tg],     v1b = g_h[r1 * DM + 2 * tg + 1];
        float v2a, v3a, v2b, v3b;
        if (tg < 3) {
            v2a = g_h[r0 * DM + 8 + 2 * tg]; v3a = g_h[r0 * DM + 9 + 2 * tg];
            v2b = g_h[r1 * DM + 8 + 2 * tg]; v3b = g_h[r1 * DM + 9 + 2 * tg];
        } else {
            v2a = 1.0f; v3a = 0.f;
            v2b = 1.0f; v3b = 0.f;
        }
        float vals[4][2] = {{v0a, v1a}, {v0b, v1b}, {v2a, v3a}, {v2b, v3b}};
#pragma unroll
        for (int i = 0; i < 4; i++) {
            qhi[i] = h2pack(vals[i][0], vals[i][1]);
            __half2 hh = *(__half2*)&qhi[i];
            qlo[i] = h2pack(vals[i][0] - __low2float(hh), vals[i][1] - __high2float(hh));
        }
    }

    float O0[4] = {0.f, 0.f, 0.f, 0.f};
    float O1[4] = {0.f, 0.f, 0.f, 0.f};

    ffn_cp(sbase, 0, 0, t, layer);
    CP_COMMIT();

    for (int c = 0; c < 8; c++) {
        if (c < 7) {
            ffn_cp(sbase, (c + 1) & 1, c + 1, t, layer);
            CP_COMMIT();
            CP_WAIT(1);
        } else {
            CP_WAIT(0);
        }
        __syncthreads();

        const char* kb = smc + (c & 1) * FBUF;
        const char* vb = kb + FW1B;

        for (int step = 0; step < 4; step++) {
            const int j = jq * 64 + step * 16;
            const char* k0 = kb + (size_t)(j + g) * 16 + tg * 4;
            const char* k1 = kb + (size_t)(j + 8 + g) * 16 + tg * 4;
            uint32_t bh0[2] = { *(const uint32_t*)k0,          *(const uint32_t*)(k0 + 4096) };
            uint32_t bl0[2] = { *(const uint32_t*)(k0 + 8192), *(const uint32_t*)(k0 + 12288) };
            uint32_t bh1[2] = { *(const uint32_t*)k1,          *(const uint32_t*)(k1 + 4096) };
            uint32_t bl1[2] = { *(const uint32_t*)(k1 + 8192), *(const uint32_t*)(k1 + 12288) };

            float S0[4] = {0.f, 0.f, 0.f, 0.f}, S1[4] = {0.f, 0.f, 0.f, 0.f};
            mma16816(S0, qhi, bh0, S0);
            mma16816(S0, qhi, bl0, S0);
            mma16816(S0, qlo, bh0, S0);
            mma16816(S1, qhi, bh1, S1);
            mma16816(S1, qhi, bl1, S1);
            mma16816(S1, qlo, bh1, S1);

            float p[8];
#pragma unroll
            for (int i = 0; i < 4; i++) { p[i] = fmaxf(S0[i], 0.f); p[4 + i] = fmaxf(S1[i], 0.f); }
            uint32_t phi[4], plo[4];
#pragma unroll
            for (int i = 0; i < 4; i++) {
                phi[i] = h2pack(p[2 * i], p[2 * i + 1]);
                __half2 hh = *(__half2*)&phi[i];
                plo[i] = h2pack(p[2 * i] - __low2float(hh), p[2 * i + 1] - __high2float(hh));
            }

            const char* v0 = vb + (size_t)(j * 2 + tg * 4);
            uint32_t vh0[2] = { *(const uint32_t*)(v0 + (size_t)g * 528),
                                *(const uint32_t*)(v0 + (size_t)g * 528 + 16) };
            uint32_t vh1[2] = { *(const uint32_t*)(v0 + (size_t)(8 + g) * 528),
                                *(const uint32_t*)(v0 + (size_t)(8 + g) * 528 + 16) };
            uint32_t vl0[2] = { *(const uint32_t*)(v0 + (size_t)(16 + g) * 528),
                                *(const uint32_t*)(v0 + (size_t)(16 + g) * 528 + 16) };
            uint32_t vl1[2] = { *(const uint32_t*)(v0 + (size_t)(24 + g) * 528),
                                *(const uint32_t*)(v0 + (size_t)(24 + g) * 528 + 16) };

            mma16816(O0, phi, vh0, O0);
            mma16816(O1, phi, vh1, O1);
            mma16816(O0, plo, vh0, O0);
            mma16816(O1, plo, vh1, O1);
            mma16816(O0, phi, vl0, O0);
            mma16816(O1, phi, vl1, O1);
        }
        __syncthreads();
    }

    // merge 4 jq groups, then LN epilogue
    {
        float* osum = (float*)smc;        // 32 x 16 floats
        int lr = rw * 16 + g;
#pragma unroll
        for (int grp = 0; grp < 4; grp++) {
            if (jq == grp) {
                if (grp == 0) {
                    osum[lr * 16 + 2 * tg]           = O0[0];
                    osum[lr * 16 + 2 * tg + 1]       = O0[1];
                    osum[lr * 16 + 8 + 2 * tg]       = O1[0];
                    osum[lr * 16 + 9 + 2 * tg]       = O1[1];
                    osum[(lr + 8) * 16 + 2 * tg]     = O0[2];
                    osum[(lr + 8) * 16 + 2 * tg + 1] = O0[3];
                    osum[(lr + 8) * 16 + 8 + 2 * tg] = O1[2];
                    osum[(lr + 8) * 16 + 9 + 2 * tg] = O1[3];
                } else {
                    osum[lr * 16 + 2 * tg]           += O0[0];
                    osum[lr * 16 + 2 * tg + 1]       += O0[1];
                    osum[lr * 16 + 8 + 2 * tg]       += O1[0];
                    osum[lr * 16 + 9 + 2 * tg]       += O1[1];
                    osum[(lr + 8) * 16 + 2 * tg]     += O0[2];
                    osum[(lr + 8) * 16 + 2 * tg + 1] += O0[3];
                    osum[(lr + 8) * 16 + 8 + 2 * tg] += O1[2];
                    osum[(lr + 8) * 16 + 9 + 2 * tg] += O1[3];
                }
            }
            __syncthreads();
        }
        if (t < 32) {
            int row = blockIdx.x * 32 + t;
            float pre[14], mu = 0.f;
#pragma unroll
            for (int d = 0; d < 14; d++) {
                float v = osum[t * 16 + d] + __ldg(b2 + d) + g_h[row * DM + d];
                pre[d] = v; mu += v;
            }
            mu *= (1.f / 14.f);
            float var = 0.f;
#pragma unroll
            for (int d = 0; d < 14; d++) { float z = pre[d] - mu; var = fmaf(z, z, var); }
            float rs = rsqrtf(var * (1.f / 14.f) + EPS);
#pragma unroll
            for (int d = 0; d < 14; d++)
                g_h[row * DM + d] = (pre[d] - mu) * rs * __ldg(lng + d) + __ldg(lnb + d);
        }
    }
}

// ---------------- head 1 ----------------
__global__ void __launch_bounds__(256, 1)
head1_kernel(const float* __restrict__ w1, const float* __restrict__ b1f,
             const float* __restrict__ w2, const float* __restrict__ b2f,
             float* __restrict__ out) {
    int n = blockIdx.x * 256 + threadIdx.x;
    float h[14];
#pragma unroll
    for (int d = 0; d < 14; d++) h[d] = g_h[n * DM + d];
    float size = __ldg(b2f);
#pragma unroll
    for (int d2 = 0; d2 < 14; d2++) {
        float s = __ldg(b1f + d2);
#pragma unroll
        for (int d = 0; d < 14; d++) s = fmaf(h[d], __ldg(w1 + d2 * 14 + d), s);
        size = fmaf(s, __ldg(w2 + d2), size);
    }
    out[n] = size;
    g_sizef[n] = (float)(int)size;
}

// ---------------- head 2 ----------------
__global__ void __launch_bounds__(256, 1)
head2_kernel(const float* __restrict__ x, const float* __restrict__ y,
             const float* __restrict__ w3, const float* __restrict__ b3,
             const float* __restrict__ w4, const float* __restrict__ b4,
             const float* __restrict__ w5, const float* __restrict__ b5,
             float* __restrict__ out) {
    extern __shared__ float sm[];
    float* w3s = sm;             // 13056
    float* ins = w3s + 13056;    // 816
    float* red = ins + 816;      // 128
    float* r1f = red + 128;      // 4608
    float* w4s = r1f + 4608;     // 16640
    const int t = threadIdx.x, lane = t & 31, warp = t >> 5;
    const int rbase = blockIdx.x * 16;
    for (int i = t; i < 13056; i += 256) w3s[i] = w3[i];
    for (int i = t; i < 16 * 51; i += 256) {
        int r = i / 51, c = i % 51, row = rbase + r;
        float v;
        if (c == 0)      v = g_sizef[row];
        else if (c < 15) v = x[row * DM + c - 1];
        else             v = y[row * MF + c - 15];
        ins[i] = v;
    }
    __syncthreads();

    float r1a[16];
    float b3t = __ldg(b3 + t);
#pragma unroll
    for (int r = 0; r < 16; r++) r1a[r] = b3t;
    for (int i = 0; i < 51; i++) {
        float w = w3s[t * 51 + i];
#pragma unroll
        for (int r = 0; r < 16; r++) r1a[r] = fmaf(ins[r * 51 + i], w, r1a[r]);
    }
#pragma unroll
    for (int rp = 0; rp < 8; rp++) {
        float2 v;
        v.x = fmaxf(r1a[2 * rp], 0.f);
        v.y = fmaxf(r1a[2 * rp + 1], 0.f);
        ((float2*)r1f)[t * 9 + rp] = v;
    }
    __syncthreads();

    u64 r2a2[8];
    float b4t = __ldg(b4 + t);
#pragma unroll
    for (int rp = 0; rp < 8; rp++) r2a2[rp] = pack2(b4t, b4t);
    for (int c = 0; c < 4; c++) {
        for (int i = t; i < 256 * 64; i += 256) {
            int o = i >> 6, jj = i & 63;
            w4s[o * 65 + jj] = __ldg(w4 + o * 256 + c * 64 + jj);
        }
        __syncthreads();
#pragma unroll 4
        for (int jj = 0; jj < 64; jj++) {
            float w = w4s[t * 65 + jj];
            u64 w2p = pack2(w, w);
            const float2* rp1 = ((const float2*)r1f) + (c * 64 + jj) * 9;
#pragma unroll
            for (int rp = 0; rp < 8; rp++) r2a2[rp] = fma2(f2u(rp1[rp]), w2p, r2a2[rp]);
        }
        __syncthreads();
    }

    float w5t = __ldg(w5 + t);
#pragma unroll
    for (int rp = 0; rp < 8; rp++) {
        float2 f = u2f(r2a2[rp]);
        float v0 = wsum(fmaxf(f.x, 0.f) * w5t);
        float v1 = wsum(fmaxf(f.y, 0.f) * w5t);
        if (lane == 0) {
            red[warp * 16 + 2 * rp] = v0;
            red[warp * 16 + 2 * rp + 1] = v1;
        }
    }
    __syncthreads();
    if (t < 16) {
        float s = __ldg(b5);
        for (int w = 0; w < 8; w++) s += red[w * 16 + t];
        int row = rbase + t;
        out[NROWS + row] = (g_sizef[row] != 0.f) ? s : 0.f;
    }
}

// ---------------- launcher ----------------
extern "C" void kernel_launch(void* const* d_in, const int* in_sizes, int n_in,
                              void* d_out, int out_size) {
    const float* x    = (const float*)d_in[0];
    const float* y    = (const float*)d_in[1];
    const float* wqkv = (const float*)d_in[2];
    const float* bqkv = (const float*)d_in[3];
    const float* wo   = (const float*)d_in[4];
    const float* bo   = (const float*)d_in[5];
    const float* ln1g = (const float*)d_in[6];
    const float* ln1b = (const float*)d_in[7];
    const float* ffw1 = (const float*)d_in[8];
    const float* ffb1 = (const float*)d_in[9];
    const float* ffw2 = (const float*)d_in[10];
    const float* ffb2 = (const float*)d_in[11];
    const float* ln2g = (const float*)d_in[12];
    const float* ln2b = (const float*)d_in[13];
    const float* fc1w = (const float*)d_in[14];
    const float* fc1b = (const float*)d_in[15];
    const float* fc2w = (const float*)d_in[16];
    const float* fc2b = (const float*)d_in[17];
    const float* fc3w = (const float*)d_in[18];
    const float* fc3b = (const float*)d_in[19];
    const float* fc4w = (const float*)d_in[20];
    const float* fc4b = (const float*)d_in[21];
    const float* fc5w = (const float*)d_in[22];
    const float* fc5b = (const float*)d_in[23];
    float* out = (float*)d_out;

    const int h2_smem = (13056 + 816 + 128 + 4608 + 16640) * (int)sizeof(float);
    cudaFuncSetAttribute(attn_mma_kernel, cudaFuncAttributeMaxDynamicSharedMemorySize, ATTN_SMEM);
    cudaFuncSetAttribute(ffn_mma_kernel,  cudaFuncAttributeMaxDynamicSharedMemorySize, FFN_SMEM);
    cudaFuncSetAttribute(head2_kernel,    cudaFuncAttributeMaxDynamicSharedMemorySize, h2_smem);

    wprep_all_kernel<<<16, 256>>>(ffw1, ffb1, ffw2);
    for (int l = 0; l < 2; l++) {
        qkv_prep_kernel<<<128, 256>>>(x, (l == 0) ? 1 : 0, wqkv + l * 588, bqkv + l * 42);
        attn_mma_kernel<<<512, 256, ATTN_SMEM>>>();
        combine_kernel<<<64, 128>>>(x, (l == 0) ? 1 : 0, wo + l * 196, bo + l * 14,
                                    ln1g + l * 14, ln1b + l * 14);
        ffn_mma_kernel<<<256, 256, FFN_SMEM>>>(l, ffb2 + l * 14, ln2g + l * 14, ln2b + l * 14);
    }
    head1_kernel<<<32, 256>>>(fc1w, fc1b, fc2w, fc2b, out);
    head2_kernel<<<512, 256, h2_smem>>>(x, y, fc3w, fc3b, fc4w, fc4b, fc5w, fc5b, out);
}

// round 10
// speedup vs baseline: 2.3264x; 1.1667x over previous
#include <cuda_runtime.h>
#include <cuda_fp16.h>
#include <stdint.h>

#define NROWS 8192
#define DM 14
#define MF 36
#define EPS 1e-5f
typedef unsigned long long u64;

__device__ __align__(16) float g_h[NROWS * DM];
__device__ __align__(16) float g_q[NROWS * DM];   // pre-scaled by D^-0.5*log2(e)
__device__ __align__(16) float g_part[8 * NROWS * 16];
__device__ __align__(16) __half g_kp[4 * NROWS * 8];   // [arr][key][8] f16
__device__ __align__(16) __half g_vt[32][NROWS];       // [dim-ish][key] f16
__device__ __align__(16) __half g_w1p[2 * 4 * 2048 * 8];  // per-layer W1 repack
__device__ __align__(16) __half g_w2p[2 * 32 * 2048];     // per-layer W2t repack
__device__ float g_sizef[NROWS];
__device__ float g_qn[NROWS];
__device__ float g_kmaxpart[128];

// ---- helpers ----
__device__ __forceinline__ u64 f2u(float2 v) { union { float2 f; u64 u; } c; c.f = v; return c.u; }
__device__ __forceinline__ float2 u2f(u64 u) { union { float2 f; u64 u; } c; c.u = u; return c.f; }
__device__ __forceinline__ u64 pack2(float lo, float hi) { float2 v; v.x = lo; v.y = hi; return f2u(v); }
__device__ __forceinline__ u64 fma2(u64 a, u64 b, u64 c) {
    u64 d; asm("fma.rn.f32x2 %0,%1,%2,%3;" : "=l"(d) : "l"(a), "l"(b), "l"(c)); return d;
}
__device__ __forceinline__ float ex2f(float x) {
    float y; asm("ex2.approx.f32 %0,%1;" : "=f"(y) : "f"(x)); return y;
}
__device__ __forceinline__ float wsum(float v) {
#pragma unroll
    for (int o = 16; o; o >>= 1) v += __shfl_xor_sync(0xffffffffu, v, o);
    return v;
}
__device__ __forceinline__ float wmax(float v) {
#pragma unroll
    for (int o = 16; o; o >>= 1) v = fmaxf(v, __shfl_xor_sync(0xffffffffu, v, o));
    return v;
}
__device__ __forceinline__ void cp16(uint32_t dst, const void* src) {
    asm volatile("cp.async.cg.shared.global [%0], [%1], 16;" :: "r"(dst), "l"(src));
}
#define CP_COMMIT() asm volatile("cp.async.commit_group;")
#define CP_WAIT(N)  asm volatile("cp.async.wait_group %0;" :: "n"(N))

__device__ __forceinline__ uint32_t h2pack(float a, float b) {
    __half2 h = __floats2half2_rn(a, b);
    return *(uint32_t*)&h;
}
__device__ __forceinline__ void mma16816(float* d, const uint32_t* a, const uint32_t* b, const float* c) {
    asm volatile(
        "mma.sync.aligned.m16n8k16.row.col.f32.f16.f16.f32 "
        "{%0,%1,%2,%3}, {%4,%5,%6,%7}, {%8,%9}, {%10,%11,%12,%13};"
        : "=f"(d[0]), "=f"(d[1]), "=f"(d[2]), "=f"(d[3])
        : "r"(a[0]), "r"(a[1]), "r"(a[2]), "r"(a[3]), "r"(b[0]), "r"(b[1]),
          "f"(c[0]), "f"(c[1]), "f"(c[2]), "f"(c[3]));
}

// ---------------- fused QKV projection + prep ----------------
#define QS 49
__global__ void __launch_bounds__(256, 1)
qkv_prep_kernel(const float* __restrict__ x0, int use_x,
                const float* __restrict__ W, const float* __restrict__ b) {
    __shared__ float Ws[42 * 14], bs[42], hs[64 * 14], qkvs[64 * QS], sp[2];
    const float* hin = use_x ? x0 : g_h;
    const int t = threadIdx.x;
    const int rb = blockIdx.x * 64;
    for (int i = t; i < 588; i += 256) Ws[i] = W[i];
    if (t < 42) bs[t] = b[t];
    for (int i = t; i < 64 * 14; i += 256) hs[i] = hin[rb * DM + i];
    __syncthreads();
    const float scale = rsqrtf(14.0f) * 1.44269504f;
    for (int idx = t; idx < 64 * 42; idx += 256) {
        int r = idx / 42, c = idx % 42;
        float s = bs[c];
#pragma unroll
        for (int d = 0; d < 14; d++) s = fmaf(hs[r * 14 + d], Ws[c * 14 + d], s);
        qkvs[r * QS + c] = (c < 14) ? s * scale : s;
    }
    __syncthreads();

    if (t < 64) {
        int row = rb + t;
        const float* qr = qkvs + t * QS;
        float qn = 0.f, kn = 0.f;
        float kv[14], vv[14];
#pragma unroll
        for (int d = 0; d < 14; d++) {
            float qf = qr[d];
            g_q[row * DM + d] = qf;
            qn = fmaf(qf, qf, qn);
            kv[d] = qr[14 + d]; kn = fmaf(kv[d], kv[d], kn);
            vv[d] = qr[28 + d];
        }
        g_qn[row] = sqrtf(qn);

        __half hi[16], lo[16];
#pragma unroll
        for (int d = 0; d < 14; d++) {
            hi[d] = __float2half_rn(kv[d]);
            lo[d] = __float2half_rn(kv[d] - __half2float(hi[d]));
        }
        hi[14] = __float2half_rn(1.0f); hi[15] = __float2half_rn(0.f);
        lo[14] = __float2half_rn(0.f);  lo[15] = __float2half_rn(0.f);
        {
            __half* p0 = g_kp + (0 * NROWS + row) * 8;
            __half* p1 = g_kp + (1 * NROWS + row) * 8;
            __half* p2 = g_kp + (2 * NROWS + row) * 8;
            __half* p3 = g_kp + (3 * NROWS + row) * 8;
#pragma unroll
            for (int d = 0; d < 8; d++) { p0[d] = hi[d]; p1[d] = hi[8 + d]; p2[d] = lo[d]; p3[d] = lo[8 + d]; }
        }
#pragma unroll
        for (int d = 0; d < 14; d++) {
            __half vh = __float2half_rn(vv[d]);
            g_vt[d][row] = vh;
            g_vt[16 + d][row] = __float2half_rn(vv[d] - __half2float(vh));
        }
        g_vt[14][row] = __float2half_rn(1.0f);
        g_vt[15][row] = __float2half_rn(0.f);
        g_vt[30][row] = __float2half_rn(0.f);
        g_vt[31][row] = __float2half_rn(0.f);

        kn = wmax(kn);
        if ((t & 31) == 0) sp[t >> 5] = kn;
    }
    __syncthreads();
    if (t == 0) g_kmaxpart[blockIdx.x] = fmaxf(sp[0], sp[1]);
}

// ---------------- mma.sync flash attention, 8-way key split ----------------
#define KBUF 16384
#define BUFSTRIDE (16384 + 16896)
#define ATTN_SMEM (2 * BUFSTRIDE)
__device__ __forceinline__ void tile_cp2(uint32_t sbase, int buf, int key0c, int t) {
    uint32_t dst = sbase + (uint32_t)buf * BUFSTRIDE;
#pragma unroll
    for (int s = 0; s < 4; s++) {
        int i = t + s * 256;
        int a = i >> 8, key = i & 255;
        cp16(dst + (uint32_t)a * 4096 + (uint32_t)key * 16,
             g_kp + ((size_t)a * NROWS + key0c + key) * 8);
    }
#pragma unroll
    for (int s = 0; s < 4; s++) {
        int i = t + s * 256;
        int row = i >> 5, seg = i & 31;
        cp16(dst + KBUF + (uint32_t)row * 528 + (uint32_t)seg * 16,
             &g_vt[row][key0c + seg * 8]);
    }
}

__global__ void __launch_bounds__(256, 3)
attn_mma_kernel() {
    extern __shared__ char smc[];
    const int t = threadIdx.x, lane = t & 31, warp = t >> 5;
    const int g = lane >> 2, tg = lane & 3;
    const int tile = blockIdx.x >> 3, part = blockIdx.x & 7;
    const int key0 = part * 1024;
    const uint32_t sbase = (uint32_t)__cvta_generic_to_shared(smc);

    float mk2 = 0.f;
    for (int i = lane; i < 128; i += 32) mk2 = fmaxf(mk2, __ldg(g_kmaxpart + i));
    mk2 = wmax(mk2);
    const float maxk = sqrtf(mk2);

    const int qbase = tile * 128 + warp * 16;
    uint32_t qhi[4], qlo[4];
    {
        int r0 = qbase + g, r1 = r0 + 8;
        float v0a = g_q[r0 * DM + 2 * tg],     v1a = g_q[r0 * DM + 2 * tg + 1];
        float v0b = g_q[r1 * DM + 2 * tg],     v1b = g_q[r1 * DM + 2 * tg + 1];
        float v2a, v3a, v2b, v3b;
        if (tg < 3) {
            v2a = g_q[r0 * DM + 8 + 2 * tg]; v3a = g_q[r0 * DM + 9 + 2 * tg];
            v2b = g_q[r1 * DM + 8 + 2 * tg]; v3b = g_q[r1 * DM + 9 + 2 * tg];
        } else {
            v2a = -__ldg(g_qn + r0) * maxk; v3a = 0.f;
            v2b = -__ldg(g_qn + r1) * maxk; v3b = 0.f;
        }
        float vals[4][2] = {{v0a, v1a}, {v0b, v1b}, {v2a, v3a}, {v2b, v3b}};
#pragma unroll
        for (int i = 0; i < 4; i++) {
            qhi[i] = h2pack(vals[i][0], vals[i][1]);
            __half2 hh = *(__half2*)&qhi[i];
            qlo[i] = h2pack(vals[i][0] - __low2float(hh), vals[i][1] - __high2float(hh));
        }
    }

    float O0[4] = {0.f, 0.f, 0.f, 0.f};
    float O1[4] = {0.f, 0.f, 0.f, 0.f};

    tile_cp2(sbase, 0, key0, t);
    CP_COMMIT();

    for (int c = 0; c < 4; c++) {
        if (c < 3) {
            tile_cp2(sbase, (c + 1) & 1, key0 + (c + 1) * 256, t);
            CP_COMMIT();
            CP_WAIT(1);
        } else {
            CP_WAIT(0);
        }
        __syncthreads();

        const char* kb = smc + (c & 1) * BUFSTRIDE;
        const char* vb = kb + KBUF;

        for (int j = 0; j < 256; j += 16) {
            const char* k0 = kb + (size_t)(j + g) * 16 + tg * 4;
            const char* k1 = kb + (size_t)(j + 8 + g) * 16 + tg * 4;
            uint32_t bh0[2] = { *(const uint32_t*)k0,          *(const uint32_t*)(k0 + 4096) };
            uint32_t bl0[2] = { *(const uint32_t*)(k0 + 8192), *(const uint32_t*)(k0 + 12288) };
            uint32_t bh1[2] = { *(const uint32_t*)k1,          *(const uint32_t*)(k1 + 4096) };
            uint32_t bl1[2] = { *(const uint32_t*)(k1 + 8192), *(const uint32_t*)(k1 + 12288) };

            float S0[4] = {0.f, 0.f, 0.f, 0.f}, S1[4] = {0.f, 0.f, 0.f, 0.f};
            mma16816(S0, qhi, bh0, S0);
            mma16816(S0, qhi, bl0, S0);
            mma16816(S0, qlo, bh0, S0);
            mma16816(S1, qhi, bh1, S1);
            mma16816(S1, qhi, bl1, S1);
            mma16816(S1, qlo, bh1, S1);

            float p[8];
#pragma unroll
            for (int i = 0; i < 4; i++) { p[i] = ex2f(S0[i]); p[4 + i] = ex2f(S1[i]); }
            uint32_t phi[4], plo[4];
#pragma unroll
            for (int i = 0; i < 4; i++) {
                phi[i] = h2pack(p[2 * i], p[2 * i + 1]);
                __half2 hh = *(__half2*)&phi[i];
                plo[i] = h2pack(p[2 * i] - __low2float(hh), p[2 * i + 1] - __high2float(hh));
            }

            const char* v0 = vb + (size_t)(j * 2 + tg * 4);
            uint32_t vh0[2] = { *(const uint32_t*)(v0 + (size_t)g * 528),
                                *(const uint32_t*)(v0 + (size_t)g * 528 + 16) };
            uint32_t vh1[2] = { *(const uint32_t*)(v0 + (size_t)(8 + g) * 528),
                                *(const uint32_t*)(v0 + (size_t)(8 + g) * 528 + 16) };
            uint32_t vl0[2] = { *(const uint32_t*)(v0 + (size_t)(16 + g) * 528),
                                *(const uint32_t*)(v0 + (size_t)(16 + g) * 528 + 16) };
            uint32_t vl1[2] = { *(const uint32_t*)(v0 + (size_t)(24 + g) * 528),
                                *(const uint32_t*)(v0 + (size_t)(24 + g) * 528 + 16) };

            mma16816(O0, phi, vh0, O0);
            mma16816(O1, phi, vh1, O1);
            mma16816(O0, plo, vh0, O0);
            mma16816(O1, plo, vh1, O1);
            mma16816(O0, phi, vl0, O0);
            mma16816(O1, phi, vl1, O1);
        }
        __syncthreads();
    }

    {
        int r0 = qbase + g;
        float* d0 = g_part + ((size_t)part * NROWS + r0) * 16;
        float* d1 = g_part + ((size_t)part * NROWS + r0 + 8) * 16;
        *(float2*)(d0 + 2 * tg)     = make_float2(O0[0], O0[1]);
        *(float2*)(d0 + 8 + 2 * tg) = make_float2(O1[0], O1[1]);
        *(float2*)(d1 + 2 * tg)     = make_float2(O0[2], O0[3]);
        *(float2*)(d1 + 8 + 2 * tg) = make_float2(O1[2], O1[3]);
    }
}

// ---------------- combine: 8 threads/row, shuffle-distributed ----------------
// grid 256 x 256 thr; 32 rows/CTA; lane group of 8 owns one row.
__global__ void __launch_bounds__(256, 2)
combine_kernel(const float* __restrict__ x0, int use_x,
               const float* __restrict__ Wo, const float* __restrict__ bo,
               const float* __restrict__ lng, const float* __restrict__ lnb) {
    __shared__ float wos[196], bos[14];
    const int t = threadIdx.x, lane = t & 31;
    for (int i = t; i < 196; i += 256) wos[i] = Wo[i];
    if (t < 14) bos[t] = bo[t];
    __syncthreads();
    const float* hin = use_x ? x0 : g_h;
    const int row = blockIdx.x * 32 + (t >> 3);
    const int e = lane & 7;

    float2 acc = make_float2(0.f, 0.f);
#pragma unroll
    for (int p = 0; p < 8; p++) {
        float2 v = ((const float2*)(g_part + ((size_t)p * NROWS + row) * 16))[e];
        acc.x += v.x; acc.y += v.y;
    }
    float l = __shfl_sync(0xffffffffu, acc.x, lane | 7);
    float inv = 1.f / l;
    float ax = acc.x * inv, ay = acc.y * inv;
    float a[14];
    const int base = lane & 24;
#pragma unroll
    for (int dp = 0; dp < 7; dp++) {
        a[2 * dp]     = __shfl_sync(0xffffffffu, ax, base + dp);
        a[2 * dp + 1] = __shfl_sync(0xffffffffu, ay, base + dp);
    }
    float pre0 = 0.f, pre1 = 0.f;
    if (e < 7) {
        int d2 = 2 * e;
        pre0 = bos[d2]; pre1 = bos[d2 + 1];
#pragma unroll
        for (int d = 0; d < 14; d++) {
            pre0 = fmaf(a[d], wos[d2 * 14 + d], pre0);
            pre1 = fmaf(a[d], wos[(d2 + 1) * 14 + d], pre1);
        }
        pre0 += hin[row * DM + d2];
        pre1 += hin[row * DM + d2 + 1];
    }
    float s = pre0 + pre1;
#pragma unroll
    for (int o = 4; o; o >>= 1) s += __shfl_xor_sync(0xffffffffu, s, o);
    float mu = s * (1.f / 14.f);
    float z0 = (e < 7) ? pre0 - mu : 0.f;
    float z1 = (e < 7) ? pre1 - mu : 0.f;
    float v = z0 * z0 + z1 * z1;
#pragma unroll
    for (int o = 4; o; o >>= 1) v += __shfl_xor_sync(0xffffffffu, v, o);
    float rs = rsqrtf(v * (1.f / 14.f) + EPS);
    if (e < 7) {
        int d2 = 2 * e;
        g_h[row * DM + d2]     = z0 * rs * __ldg(lng + d2)     + __ldg(lnb + d2);
        g_h[row * DM + d2 + 1] = z1 * rs * __ldg(lng + d2 + 1) + __ldg(lnb + d2 + 1);
    }
}

// ---------------- wprep (both layers, once) ----------------
__global__ void __launch_bounds__(256, 1)
wprep_all_kernel(const float* __restrict__ W1a, const float* __restrict__ b1a,
                 const float* __restrict__ W2a) {
    int idx = blockIdx.x * 256 + threadIdx.x;
    int layer = idx >> 11, j = idx & 2047;
    const float* W1 = W1a + layer * 28672;
    const float* b1 = b1a + layer * 2048;
    const float* W2 = W2a + layer * 28672;
    __half* w1p = g_w1p + layer * 65536;
    __half* w2p = g_w2p + layer * 65536;

    __half hi[16], lo[16];
#pragma unroll
    for (int d = 0; d < 14; d++) {
        float w = W1[j * 14 + d];
        hi[d] = __float2half_rn(w);
        lo[d] = __float2half_rn(w - __half2float(hi[d]));
    }
    {
        float bb = __ldg(b1 + j);
        hi[14] = __float2half_rn(bb);
        lo[14] = __float2half_rn(bb - __half2float(hi[14]));
        hi[15] = __float2half_rn(0.f); lo[15] = __float2half_rn(0.f);
    }
    {
        __half* p0 = w1p + (0 * 2048 + j) * 8;
        __half* p1 = w1p + (1 * 2048 + j) * 8;
        __half* p2 = w1p + (2 * 2048 + j) * 8;
        __half* p3 = w1p + (3 * 2048 + j) * 8;
#pragma unroll
        for (int d = 0; d < 8; d++) { p0[d] = hi[d]; p1[d] = hi[8 + d]; p2[d] = lo[d]; p3[d] = lo[8 + d]; }
    }
#pragma unroll
    for (int d = 0; d < 14; d++) {
        float w = W2[d * 2048 + j];
        __half wh = __float2half_rn(w);
        w2p[d * 2048 + j] = wh;
        w2p[(16 + d) * 2048 + j] = __float2half_rn(w - __half2float(wh));
    }
    w2p[14 * 2048 + j] = __float2half_rn(0.f);
    w2p[15 * 2048 + j] = __float2half_rn(0.f);
    w2p[30 * 2048 + j] = __float2half_rn(0.f);
    w2p[31 * 2048 + j] = __float2half_rn(0.f);
}

// ---------------- FFN via mma.sync + fused head1 on layer 1 ----------------
#define FW1B 16384
#define FBUF (FW1B + 16896)
#define FFN_SMEM (2 * FBUF)
__device__ __forceinline__ void ffn_cp(uint32_t sbase, int buf, int chunk, int t, int layer) {
    uint32_t dst = sbase + (uint32_t)buf * FBUF;
    const __half* w1p = g_w1p + layer * 65536;
    const __half* w2p = g_w2p + layer * 65536;
#pragma unroll
    for (int s = 0; s < 4; s++) {
        int i = t + s * 256;
        int a = i >> 8, j = i & 255;
        cp16(dst + (uint32_t)a * 4096 + (uint32_t)j * 16,
             w1p + ((size_t)a * 2048 + chunk * 256 + j) * 8);
    }
#pragma unroll
    for (int s = 0; s < 4; s++) {
        int i = t + s * 256;
        int row = i >> 5, seg = i & 31;
        cp16(dst + FW1B + (uint32_t)row * 528 + (uint32_t)seg * 16,
             w2p + (size_t)row * 2048 + chunk * 256 + seg * 8);
    }
}

__global__ void __launch_bounds__(256, 2)
ffn_mma_kernel(int layer, const float* __restrict__ b2,
               const float* __restrict__ lng, const float* __restrict__ lnb,
               const float* __restrict__ fc1w, const float* __restrict__ fc1b,
               const float* __restrict__ fc2w, const float* __restrict__ fc2b,
               float* __restrict__ out) {
    extern __shared__ char smc[];
    const int t = threadIdx.x, lane = t & 31, warp = t >> 5;
    const int g = lane >> 2, tg = lane & 3;
    const int rw = warp & 1, jq = warp >> 1;
    const uint32_t sbase = (uint32_t)__cvta_generic_to_shared(smc);
    const int rbase = blockIdx.x * 32 + rw * 16;

    uint32_t qhi[4], qlo[4];
    {
        int r0 = rbase + g, r1 = r0 + 8;
        float v0a = g_h[r0 * DM + 2 * tg],     v1a = g_h[r0 * DM + 2 * tg + 1];
        float v0b = g_h[r1 * DM + 2 * tg],     v1b = g_h[r1 * DM + 2 * tg + 1];
        float v2a, v3a, v2b, v3b;
        if (tg < 3) {
            v2a = g_h[r0 * DM + 8 + 2 * tg]; v3a = g_h[r0 * DM + 9 + 2 * tg];
            v2b = g_h[r1 * DM + 8 + 2 * tg]; v3b = g_h[r1 * DM + 9 + 2 * tg];
        } else {
            v2a = 1.0f; v3a = 0.f;
            v2b = 1.0f; v3b = 0.f;
        }
        float vals[4][2] = {{v0a, v1a}, {v0b, v1b}, {v2a, v3a}, {v2b, v3b}};
#pragma unroll
        for (int i = 0; i < 4; i++) {
            qhi[i] = h2pack(vals[i][0], vals[i][1]);
            __half2 hh = *(__half2*)&qhi[i];
            qlo[i] = h2pack(vals[i][0] - __low2float(hh), vals[i][1] - __high2float(hh));
        }
    }

    float O0[4] = {0.f, 0.f, 0.f, 0.f};
    float O1[4] = {0.f, 0.f, 0.f, 0.f};

    ffn_cp(sbase, 0, 0, t, layer);
    CP_COMMIT();

    for (int c = 0; c < 8; c++) {
        if (c < 7) {
            ffn_cp(sbase, (c + 1) & 1, c + 1, t, layer);
            CP_COMMIT();
            CP_WAIT(1);
        } else {
            CP_WAIT(0);
        }
        __syncthreads();

        const char* kb = smc + (c & 1) * FBUF;
        const char* vb = kb + FW1B;

        for (int step = 0; step < 4; step++) {
            const int j = jq * 64 + step * 16;
            const char* k0 = kb + (size_t)(j + g) * 16 + tg * 4;
            const char* k1 = kb + (size_t)(j + 8 + g) * 16 + tg * 4;
            uint32_t bh0[2] = { *(const uint32_t*)k0,          *(const uint32_t*)(k0 + 4096) };
            uint32_t bl0[2] = { *(const uint32_t*)(k0 + 8192), *(const uint32_t*)(k0 + 12288) };
            uint32_t bh1[2] = { *(const uint32_t*)k1,          *(const uint32_t*)(k1 + 4096) };
            uint32_t bl1[2] = { *(const uint32_t*)(k1 + 8192), *(const uint32_t*)(k1 + 12288) };

            float S0[4] = {0.f, 0.f, 0.f, 0.f}, S1[4] = {0.f, 0.f, 0.f, 0.f};
            mma16816(S0, qhi, bh0, S0);
            mma16816(S0, qhi, bl0, S0);
            mma16816(S0, qlo, bh0, S0);
            mma16816(S1, qhi, bh1, S1);
            mma16816(S1, qhi, bl1, S1);
            mma16816(S1, qlo, bh1, S1);

            float p[8];
#pragma unroll
            for (int i = 0; i < 4; i++) { p[i] = fmaxf(S0[i], 0.f); p[4 + i] = fmaxf(S1[i], 0.f); }
            uint32_t phi[4], plo[4];
#pragma unroll
            for (int i = 0; i < 4; i++) {
                phi[i] = h2pack(p[2 * i], p[2 * i + 1]);
                __half2 hh = *(__half2*)&phi[i];
                plo[i] = h2pack(p[2 * i] - __low2float(hh), p[2 * i + 1] - __high2float(hh));
            }

            const char* v0 = vb + (size_t)(j * 2 + tg * 4);
            uint32_t vh0[2] = { *(const uint32_t*)(v0 + (size_t)g * 528),
                                *(const uint32_t*)(v0 + (size_t)g * 528 + 16) };
            uint32_t vh1[2] = { *(const uint32_t*)(v0 + (size_t)(8 + g) * 528),
                                *(const uint32_t*)(v0 + (size_t)(8 + g) * 528 + 16) };
            uint32_t vl0[2] = { *(const uint32_t*)(v0 + (size_t)(16 + g) * 528),
                                *(const uint32_t*)(v0 + (size_t)(16 + g) * 528 + 16) };
            uint32_t vl1[2] = { *(const uint32_t*)(v0 + (size_t)(24 + g) * 528),
                                *(const uint32_t*)(v0 + (size_t)(24 + g) * 528 + 16) };

            mma16816(O0, phi, vh0, O0);
            mma16816(O1, phi, vh1, O1);
            mma16816(O0, plo, vh0, O0);
            mma16816(O1, plo, vh1, O1);
            mma16816(O0, phi, vl0, O0);
            mma16816(O1, phi, vl1, O1);
        }
        __syncthreads();
    }

    {
        float* osum = (float*)smc;        // 32 x 16 floats
        int lr = rw * 16 + g;
#pragma unroll
        for (int grp = 0; grp < 4; grp++) {
            if (jq == grp) {
                if (grp == 0) {
                    osum[lr * 16 + 2 * tg]           = O0[0];
                    osum[lr * 16 + 2 * tg + 1]       = O0[1];
                    osum[lr * 16 + 8 + 2 * tg]       = O1[0];
                    osum[lr * 16 + 9 + 2 * tg]       = O1[1];
                    osum[(lr + 8) * 16 + 2 * tg]     = O0[2];
                    osum[(lr + 8) * 16 + 2 * tg + 1] = O0[3];
                    osum[(lr + 8) * 16 + 8 + 2 * tg] = O1[2];
                    osum[(lr + 8) * 16 + 9 + 2 * tg] = O1[3];
                } else {
                    osum[lr * 16 + 2 * tg]           += O0[0];
                    osum[lr * 16 + 2 * tg + 1]       += O0[1];
                    osum[lr * 16 + 8 + 2 * tg]       += O1[0];
                    osum[lr * 16 + 9 + 2 * tg]       += O1[1];
                    osum[(lr + 8) * 16 + 2 * tg]     += O0[2];
                    osum[(lr + 8) * 16 + 2 * tg + 1] += O0[3];
                    osum[(lr + 8) * 16 + 8 + 2 * tg] += O1[2];
                    osum[(lr + 8) * 16 + 9 + 2 * tg] += O1[3];
                }
            }
            __syncthreads();
        }
        if (t < 32) {
            int row = blockIdx.x * 32 + t;
            float pre[14], mu = 0.f;
#pragma unroll
            for (int d = 0; d < 14; d++) {
                float v = osum[t * 16 + d] + __ldg(b2 + d) + g_h[row * DM + d];
                pre[d] = v; mu += v;
            }
            mu *= (1.f / 14.f);
            float var = 0.f;
#pragma unroll
            for (int d = 0; d < 14; d++) { float z = pre[d] - mu; var = fmaf(z, z, var); }
            float rs = rsqrtf(var * (1.f / 14.f) + EPS);
            float hv[14];
#pragma unroll
            for (int d = 0; d < 14; d++) {
                hv[d] = (pre[d] - mu) * rs * __ldg(lng + d) + __ldg(lnb + d);
                g_h[row * DM + d] = hv[d];
            }
            if (layer == 1) {
                // fused head1: size = fc2(fc1(h))
                float size = __ldg(fc2b);
#pragma unroll
                for (int d2 = 0; d2 < 14; d2++) {
                    float s = __ldg(fc1b + d2);
#pragma unroll
                    for (int d = 0; d < 14; d++) s = fmaf(hv[d], __ldg(fc1w + d2 * 14 + d), s);
                    size = fmaf(s, __ldg(fc2w + d2), size);
                }
                out[row] = size;
                g_sizef[row] = (float)(int)size;
            }
        }
    }
}

// ---------------- head 2: 32 rows/CTA ----------------
__global__ void __launch_bounds__(256, 1)
head2_kernel(const float* __restrict__ x, const float* __restrict__ y,
             const float* __restrict__ w3, const float* __restrict__ b3,
             const float* __restrict__ w4, const float* __restrict__ b4,
             const float* __restrict__ w5, const float* __restrict__ b5,
             float* __restrict__ out) {
    extern __shared__ float sm[];
    float* w3s = sm;             // 13056
    float* ins = w3s + 13056;    // 1632
    float* red = ins + 1632;     // 256
    float* r1f = red + 256;      // 256 x 17 f2 = 8704 floats
    float* w4s = r1f + 8704;     // 16640
    const int t = threadIdx.x, lane = t & 31, warp = t >> 5;
    const int rbase = blockIdx.x * 32;
    for (int i = t; i < 13056; i += 256) w3s[i] = w3[i];
    for (int i = t; i < 32 * 51; i += 256) {
        int r = i / 51, c = i % 51, row = rbase + r;
        float v;
        if (c == 0)      v = g_sizef[row];
        else if (c < 15) v = x[row * DM + c - 1];
        else             v = y[row * MF + c - 15];
        ins[i] = v;
    }
    __syncthreads();

    // stage A: r1[neuron t][32 rows]
    float r1a[32];
    float b3t = __ldg(b3 + t);
#pragma unroll
    for (int r = 0; r < 32; r++) r1a[r] = b3t;
    for (int i = 0; i < 51; i++) {
        float w = w3s[t * 51 + i];
#pragma unroll
        for (int r = 0; r < 32; r++) r1a[r] = fmaf(ins[r * 51 + i], w, r1a[r]);
    }
#pragma unroll
    for (int rp = 0; rp < 16; rp++) {
        float2 v;
        v.x = fmaxf(r1a[2 * rp], 0.f);
        v.y = fmaxf(r1a[2 * rp + 1], 0.f);
        ((float2*)r1f)[t * 17 + rp] = v;
    }
    __syncthreads();

    // stage B: r2[o=t][32 rows], w4 staged through smem in 64-wide chunks
    u64 r2a2[16];
    float b4t = __ldg(b4 + t);
#pragma unroll
    for (int rp = 0; rp < 16; rp++) r2a2[rp] = pack2(b4t, b4t);
    for (int c = 0; c < 4; c++) {
        for (int i = t; i < 256 * 64; i += 256) {
            int o = i >> 6, jj = i & 63;
            w4s[o * 65 + jj] = __ldg(w4 + o * 256 + c * 64 + jj);
        }
        __syncthreads();
#pragma unroll 2
        for (int jj = 0; jj < 64; jj++) {
            float w = w4s[t * 65 + jj];
            u64 w2p = pack2(w, w);
            const float2* rp1 = ((const float2*)r1f) + (c * 64 + jj) * 17;
#pragma unroll
            for (int rp = 0; rp < 16; rp++) r2a2[rp] = fma2(f2u(rp1[rp]), w2p, r2a2[rp]);
        }
        __syncthreads();
    }

    float w5t = __ldg(w5 + t);
#pragma unroll
    for (int rp = 0; rp < 16; rp++) {
        float2 f = u2f(r2a2[rp]);
        float v0 = wsum(fmaxf(f.x, 0.f) * w5t);
        float v1 = wsum(fmaxf(f.y, 0.f) * w5t);
        if (lane == 0) {
            red[warp * 32 + 2 * rp] = v0;
            red[warp * 32 + 2 * rp + 1] = v1;
        }
    }
    __syncthreads();
    if (t < 32) {
        float s = __ldg(b5);
        for (int w = 0; w < 8; w++) s += red[w * 32 + t];
        int row = rbase + t;
        out[NROWS + row] = (g_sizef[row] != 0.f) ? s : 0.f;
    }
}

// ---------------- launcher ----------------
extern "C" void kernel_launch(void* const* d_in, const int* in_sizes, int n_in,
                              void* d_out, int out_size) {
    const float* x    = (const float*)d_in[0];
    const float* y    = (const float*)d_in[1];
    const float* wqkv = (const float*)d_in[2];
    const float* bqkv = (const float*)d_in[3];
    const float* wo   = (const float*)d_in[4];
    const float* bo   = (const float*)d_in[5];
    const float* ln1g = (const float*)d_in[6];
    const float* ln1b = (const float*)d_in[7];
    const float* ffw1 = (const float*)d_in[8];
    const float* ffb1 = (const float*)d_in[9];
    const float* ffw2 = (const float*)d_in[10];
    const float* ffb2 = (const float*)d_in[11];
    const float* ln2g = (const float*)d_in[12];
    const float* ln2b = (const float*)d_in[13];
    const float* fc1w = (const float*)d_in[14];
    const float* fc1b = (const float*)d_in[15];
    const float* fc2w = (const float*)d_in[16];
    const float* fc2b = (const float*)d_in[17];
    const float* fc3w = (const float*)d_in[18];
    const float* fc3b = (const float*)d_in[19];
    const float* fc4w = (const float*)d_in[20];
    const float* fc4b = (const float*)d_in[21];
    const float* fc5w = (const float*)d_in[22];
    const float* fc5b = (const float*)d_in[23];
    float* out = (float*)d_out;

    const int h2_smem = (13056 + 1632 + 256 + 8704 + 16640) * (int)sizeof(float);
    cudaFuncSetAttribute(attn_mma_kernel, cudaFuncAttributeMaxDynamicSharedMemorySize, ATTN_SMEM);
    cudaFuncSetAttribute(ffn_mma_kernel,  cudaFuncAttributeMaxDynamicSharedMemorySize, FFN_SMEM);
    cudaFuncSetAttribute(head2_kernel,    cudaFuncAttributeMaxDynamicSharedMemorySize, h2_smem);

    wprep_all_kernel<<<16, 256>>>(ffw1, ffb1, ffw2);
    for (int l = 0; l < 2; l++) {
        qkv_prep_kernel<<<128, 256>>>(x, (l == 0) ? 1 : 0, wqkv + l * 588, bqkv + l * 42);
        attn_mma_kernel<<<512, 256, ATTN_SMEM>>>();
        combine_kernel<<<256, 256>>>(x, (l == 0) ? 1 : 0, wo + l * 196, bo + l * 14,
                                     ln1g + l * 14, ln1b + l * 14);
        ffn_mma_kernel<<<256, 256, FFN_SMEM>>>(l, ffb2 + l * 14, ln2g + l * 14, ln2b + l * 14,
                                               fc1w, fc1b, fc2w, fc2b, out);
    }
    head2_kernel<<<256, 256, h2_smem>>>(x, y, fc3w, fc3b, fc4w, fc4b, fc5w, fc5b, out);
}